// round 2
// baseline (speedup 1.0000x reference)
#include <cuda_runtime.h>
#include <cstddef>

#define S_LEN   2048
#define B_SZ    2
#define E_DIM   512
#define H_HEADS 8
#define I_DIM   64
#define M_MEM   2048
#define FF_DIM  2048
#define K_LEN   (M_MEM + S_LEN)      // 4096
#define HI      (H_HEADS * I_DIM)    // 512
#define QKV3    (3 * HI)             // 1536

// ---------------- scratch (device globals; no allocations allowed) ----------
__device__ float g_qkv   [(size_t)K_LEN * B_SZ * QKV3];          // (K*B, 3HI)   50 MB
__device__ float g_r     [(size_t)K_LEN * HI];                   // (K, H*I)      8 MB
__device__ float g_score [(size_t)B_SZ * H_HEADS * S_LEN * K_LEN]; // (z,s,k)   536 MB
__device__ float g_attn  [(size_t)S_LEN * B_SZ * E_DIM];         // (S,B,E)
__device__ float g_y     [(size_t)S_LEN * B_SZ * E_DIM];
__device__ float g_ao    [(size_t)S_LEN * B_SZ * E_DIM];
__device__ float g_hidden[(size_t)S_LEN * B_SZ * FF_DIM];        // 32 MB
__device__ float g_z     [(size_t)S_LEN * B_SZ * E_DIM];

// ---------------- generic SGEMM: C(M,N) = gather(A)(M,K) @ B(K,N) ------------
// Rows < splitRow come from A0, the rest from A1 (both row stride = Kd).
// 128x128 block tile, 8 k-slice, 8x8 per thread, 256 threads.
template<int BIAS, int RELU>
__global__ __launch_bounds__(256)
void sgemm128(const float* __restrict__ A0, const float* __restrict__ A1,
              int splitRow, const float* __restrict__ Bm,
              const float* __restrict__ bias, float* __restrict__ C,
              int Mrows, int N, int Kd)
{
    __shared__ __align__(16) float As[8][128];
    __shared__ __align__(16) float Bs[8][128];
    const int tid = threadIdx.x;
    const int bm  = blockIdx.y * 128;
    const int bn  = blockIdx.x * 128;

    const int aRow = tid >> 1;            // 0..127
    const int aCol = (tid & 1) * 4;       // 0 or 4
    const int bRow = tid >> 5;            // 0..7
    const int bCol = (tid & 31) * 4;      // 0..124
    const int ty   = tid >> 4;            // 0..15
    const int tx   = tid & 15;            // 0..15

    const int grow = bm + aRow;
    const float* aPtr = (grow < splitRow)
        ? (A0 + (size_t)grow * Kd)
        : (A1 + (size_t)(grow - splitRow) * Kd);

    float acc[8][8] = {};

    for (int k0 = 0; k0 < Kd; k0 += 8) {
        float4 av = *(const float4*)(aPtr + k0 + aCol);
        As[aCol + 0][aRow] = av.x;
        As[aCol + 1][aRow] = av.y;
        As[aCol + 2][aRow] = av.z;
        As[aCol + 3][aRow] = av.w;
        *(float4*)&Bs[bRow][bCol] =
            *(const float4*)(Bm + (size_t)(k0 + bRow) * N + bn + bCol);
        __syncthreads();
        #pragma unroll
        for (int kk = 0; kk < 8; kk++) {
            float ra[8], rb[8];
            #pragma unroll
            for (int i = 0; i < 8; i++) ra[i] = As[kk][ty * 8 + i];
            #pragma unroll
            for (int j = 0; j < 8; j++) rb[j] = Bs[kk][tx * 8 + j];
            #pragma unroll
            for (int i = 0; i < 8; i++)
                #pragma unroll
                for (int j = 0; j < 8; j++)
                    acc[i][j] += ra[i] * rb[j];
        }
        __syncthreads();
    }

    #pragma unroll
    for (int i = 0; i < 8; i++) {
        const int row = bm + ty * 8 + i;
        float* cp = C + (size_t)row * N + bn + tx * 8;
        #pragma unroll
        for (int j = 0; j < 8; j++) {
            float v = acc[i][j];
            if (BIAS) v += bias[bn + tx * 8 + j];
            if (RELU) v = fmaxf(v, 0.f);
            cp[j] = v;
        }
    }
}

// ---------------- fused score kernel: AC + rel-shifted BD, masked ------------
// For unmasked (j <= i+m):  score[i,j] = (dot(q+u, kk[j]) + dot(q+v, r[j+S-1-i])) / 8
// The rel_shift wrap region coincides exactly with the causal mask, so the
// shifted index j+S-1-i is always in [0, K) where we store.
__global__ __launch_bounds__(256)
void score_kernel(const float* __restrict__ u, const float* __restrict__ v)
{
    __shared__ __align__(16) float qu[32][68];
    __shared__ __align__(16) float qv[32][68];
    __shared__ __align__(16) float kks[32][68];
    __shared__ __align__(16) float rs[64][68];

    const int j0 = blockIdx.x * 32;
    const int i0 = blockIdx.y * 32;
    if (j0 > i0 + 31 + M_MEM) return;          // fully masked tile
    const int z = blockIdx.z;                  // b*H + h
    const int b = z >> 3, h = z & 7;
    const int tid = threadIdx.x;

    for (int idx = tid; idx < 32 * 64; idx += 256) {
        const int row = idx >> 6, col = idx & 63;
        const float qval =
            g_qkv[((size_t)(M_MEM + i0 + row) * B_SZ + b) * QKV3 + h * I_DIM + col];
        qu[row][col] = qval + u[h * I_DIM + col];
        qv[row][col] = qval + v[h * I_DIM + col];
        kks[row][col] =
            g_qkv[((size_t)(j0 + row) * B_SZ + b) * QKV3 + HI + h * I_DIM + col];
    }
    const int jjmin = j0 + S_LEN - 32 - i0;    // >= 0 always
    for (int idx = tid; idx < 64 * 64; idx += 256) {
        const int row = idx >> 6, col = idx & 63;
        const int jj = jjmin + row;
        rs[row][col] = (jj < K_LEN) ? g_r[(size_t)jj * HI + h * I_DIM + col] : 0.f;
    }
    __syncthreads();

    const int tx = tid & 31;                   // j within tile
    const int ty = tid >> 5;                   // 0..7
    const float scale = 0.125f;                // 1/sqrt(64)

    #pragma unroll
    for (int rep = 0; rep < 4; rep++) {
        const int il = ty + rep * 8;
        const int i  = i0 + il;
        const int j  = j0 + tx;
        if (j <= i + M_MEM) {
            const float4* qup = (const float4*)qu[il];
            const float4* qvp = (const float4*)qv[il];
            const float4* kp  = (const float4*)kks[tx];
            const float4* rp  = (const float4*)rs[tx - il + 31];
            float ac = 0.f, bd = 0.f;
            #pragma unroll
            for (int ii = 0; ii < 16; ii++) {
                float4 a = qup[ii], k4 = kp[ii];
                ac += a.x * k4.x + a.y * k4.y + a.z * k4.z + a.w * k4.w;
                float4 q4 = qvp[ii], r4 = rp[ii];
                bd += q4.x * r4.x + q4.y * r4.y + q4.z * r4.z + q4.w * r4.w;
            }
            g_score[((size_t)z * S_LEN + i) * K_LEN + j] = (ac + bd) * scale;
        }
    }
}

// ---------------- softmax over valid keys; zero the masked tail --------------
// Pass 1: max. Pass 2: write exp(x-max) in place while accumulating sum.
// Pass 3: scale in place (no second exp).
__global__ __launch_bounds__(256)
void softmax_kernel()
{
    const int rowid = blockIdx.x;              // z*S + i
    const int i = rowid & (S_LEN - 1);
    float* p = g_score + (size_t)rowid * K_LEN;
    const int jmax = i + M_MEM + 1;            // <= K_LEN
    const int tid = threadIdx.x;
    __shared__ float red[256];

    float mx = -1e30f;
    for (int j = tid; j < jmax; j += 256) mx = fmaxf(mx, p[j]);
    red[tid] = mx; __syncthreads();
    for (int s = 128; s > 0; s >>= 1) {
        if (tid < s) red[tid] = fmaxf(red[tid], red[tid + s]);
        __syncthreads();
    }
    mx = red[0]; __syncthreads();

    float sum = 0.f;
    for (int j = tid; j < jmax; j += 256) {
        const float e = __expf(p[j] - mx);
        p[j] = e;
        sum += e;
    }
    red[tid] = sum; __syncthreads();
    for (int s = 128; s > 0; s >>= 1) {
        if (tid < s) red[tid] += red[tid + s];
        __syncthreads();
    }
    const float inv = 1.f / red[0];

    for (int j = tid; j < jmax; j += 256) p[j] *= inv;
    for (int j = jmax + tid; j < K_LEN; j += 256) p[j] = 0.f;
}

// ---------------- attn = prob @ V, k-loop bounded by causal structure --------
__global__ __launch_bounds__(256)
void attnv_kernel()
{
    __shared__ float ps[32][33];
    __shared__ float vs[32][64];
    const int i0 = blockIdx.x * 32;
    const int z = blockIdx.y;
    const int b = z >> 3, h = z & 7;
    const int tid = threadIdx.x;
    const int tx = tid & 63;                   // output col (I dim)
    const int ty = tid >> 6;                   // 0..3
    float acc[8] = {};
    const int kmax = i0 + 31 + M_MEM + 1;      // multiple of 32, <= K_LEN
    const float* srow = g_score + ((size_t)z * S_LEN + i0) * K_LEN;

    for (int k0 = 0; k0 < kmax; k0 += 32) {
        for (int idx = tid; idx < 1024; idx += 256) {
            const int r = idx >> 5, c = idx & 31;
            ps[r][c] = srow[(size_t)r * K_LEN + k0 + c];
        }
        for (int idx = tid; idx < 2048; idx += 256) {
            const int r = idx >> 6, c = idx & 63;
            vs[r][c] =
                g_qkv[((size_t)(k0 + r) * B_SZ + b) * QKV3 + 2 * HI + h * I_DIM + c];
        }
        __syncthreads();
        #pragma unroll
        for (int kk = 0; kk < 32; kk++) {
            const float vval = vs[kk][tx];
            #pragma unroll
            for (int r = 0; r < 8; r++)
                acc[r] += ps[ty + 4 * r][kk] * vval;
        }
        __syncthreads();
    }
    #pragma unroll
    for (int r = 0; r < 8; r++) {
        const int i = i0 + ty + 4 * r;
        g_attn[((size_t)i * B_SZ + b) * E_DIM + h * I_DIM + tx] = acc[r];
    }
}

// ---------------- residual (+optional extra bias) + LayerNorm ----------------
__global__ __launch_bounds__(256)
void ln_kernel(const float* __restrict__ x1, const float* __restrict__ x2,
               const float* __restrict__ extra_bias,
               const float* __restrict__ gamma, const float* __restrict__ beta,
               float* __restrict__ out)
{
    const int row = blockIdx.x;
    const int tid = threadIdx.x;
    const float* p1 = x1 + (size_t)row * E_DIM;
    const float* p2 = x2 + (size_t)row * E_DIM;
    float v0 = p1[tid] + p2[tid];
    float v1 = p1[tid + 256] + p2[tid + 256];
    if (extra_bias) { v0 += extra_bias[tid]; v1 += extra_bias[tid + 256]; }

    __shared__ float red[256];
    red[tid] = v0 + v1; __syncthreads();
    for (int s = 128; s > 0; s >>= 1) {
        if (tid < s) red[tid] += red[tid + s];
        __syncthreads();
    }
    const float mean = red[0] * (1.f / E_DIM);
    __syncthreads();
    const float d0 = v0 - mean, d1 = v1 - mean;
    red[tid] = d0 * d0 + d1 * d1; __syncthreads();
    for (int s = 128; s > 0; s >>= 1) {
        if (tid < s) red[tid] += red[tid + s];
        __syncthreads();
    }
    const float rstd = rsqrtf(red[0] * (1.f / E_DIM) + 1e-5f);
    out[(size_t)row * E_DIM + tid]       = d0 * rstd * gamma[tid]       + beta[tid];
    out[(size_t)row * E_DIM + tid + 256] = d1 * rstd * gamma[tid + 256] + beta[tid + 256];
}

// ---------------- launch ------------------------------------------------------
extern "C" void kernel_launch(void* const* d_in, const int* in_sizes, int n_in,
                              void* d_out, int out_size)
{
    const float* inputDec = (const float*)d_in[0];
    const float* posEmb   = (const float*)d_in[1];
    const float* u        = (const float*)d_in[2];
    const float* v        = (const float*)d_in[3];
    const float* memories = (const float*)d_in[4];
    const float* Wqkv     = (const float*)d_in[5];
    const float* Wr       = (const float*)d_in[6];
    const float* Wo       = (const float*)d_in[7];
    const float* ln1_g    = (const float*)d_in[8];
    const float* ln1_b    = (const float*)d_in[9];
    const float* W1       = (const float*)d_in[10];
    const float* b1       = (const float*)d_in[11];
    const float* W2       = (const float*)d_in[12];
    const float* b2       = (const float*)d_in[13];
    const float* ln2_g    = (const float*)d_in[14];
    const float* ln2_b    = (const float*)d_in[15];
    float* out = (float*)d_out;

    float *p_qkv, *p_r, *p_attn, *p_y, *p_ao, *p_h, *p_z;
    cudaGetSymbolAddress((void**)&p_qkv, g_qkv);
    cudaGetSymbolAddress((void**)&p_r, g_r);
    cudaGetSymbolAddress((void**)&p_attn, g_attn);
    cudaGetSymbolAddress((void**)&p_y, g_y);
    cudaGetSymbolAddress((void**)&p_ao, g_ao);
    cudaGetSymbolAddress((void**)&p_h, g_hidden);
    cudaGetSymbolAddress((void**)&p_z, g_z);

    // 1) qkv = concat(memories, inputDec) @ Wqkv     (8192 x 1536 x 512)
    sgemm128<0,0><<<dim3(QKV3 / 128, (K_LEN * B_SZ) / 128), 256>>>(
        memories, inputDec, M_MEM * B_SZ, Wqkv, nullptr, p_qkv,
        K_LEN * B_SZ, QKV3, E_DIM);

    // 2) r = posEmbeddings @ Wr                      (4096 x 512 x 512)
    sgemm128<0,0><<<dim3(HI / 128, K_LEN / 128), 256>>>(
        posEmb, posEmb, K_LEN, Wr, nullptr, p_r, K_LEN, HI, E_DIM);

    // 3) scores (AC + rel-shifted BD, masked)
    score_kernel<<<dim3(K_LEN / 32, S_LEN / 32, B_SZ * H_HEADS), 256>>>(u, v);

    // 4) softmax along k
    softmax_kernel<<<B_SZ * H_HEADS * S_LEN, 256>>>();

    // 5) attn = prob @ V
    attnv_kernel<<<dim3(S_LEN / 32, B_SZ * H_HEADS), 256>>>();

    // 6) y = attn @ Wo                               (4096 x 512 x 512)
    sgemm128<0,0><<<dim3(E_DIM / 128, (S_LEN * B_SZ) / 128), 256>>>(
        p_attn, p_attn, S_LEN * B_SZ, Wo, nullptr, p_y,
        S_LEN * B_SZ, E_DIM, HI);

    // 7) attn_out = LN(inputDec + y)
    ln_kernel<<<S_LEN * B_SZ, 256>>>(inputDec, p_y, nullptr, ln1_g, ln1_b, p_ao);

    // 8) hidden = relu(attn_out @ W1 + b1)           (4096 x 2048 x 512)
    sgemm128<1,1><<<dim3(FF_DIM / 128, (S_LEN * B_SZ) / 128), 256>>>(
        p_ao, p_ao, S_LEN * B_SZ, W1, b1, p_h,
        S_LEN * B_SZ, FF_DIM, E_DIM);

    // 9) z = hidden @ W2                             (4096 x 512 x 2048)
    sgemm128<0,0><<<dim3(E_DIM / 128, (S_LEN * B_SZ) / 128), 256>>>(
        p_h, p_h, S_LEN * B_SZ, W2, nullptr, p_z,
        S_LEN * B_SZ, E_DIM, FF_DIM);

    // 10) out = LN(attn_out + z + b2)
    ln_kernel<<<S_LEN * B_SZ, 256>>>(p_ao, p_z, b2, ln2_g, ln2_b, out);
}

// round 5
// speedup vs baseline: 1.6644x; 1.6644x over previous
#include <cuda_runtime.h>
#include <cstdint>
#include <cstddef>

#define S_LEN   2048
#define B_SZ    2
#define E_DIM   512
#define H_HEADS 8
#define I_DIM   64
#define M_MEM   2048
#define FF_DIM  2048
#define K_LEN   (M_MEM + S_LEN)      // 4096
#define HI      (H_HEADS * I_DIM)    // 512
#define QKV3    (3 * HI)             // 1536

// ---------------- scratch (device globals; no allocations allowed) ----------
__device__ float g_qkv   [(size_t)K_LEN * B_SZ * QKV3];            // 50 MB
__device__ float g_r     [(size_t)K_LEN * HI];                     //  8 MB
__device__ float g_score [(size_t)B_SZ * H_HEADS * S_LEN * K_LEN]; // 536 MB
__device__ float g_attn  [(size_t)S_LEN * B_SZ * E_DIM];
__device__ float g_y     [(size_t)S_LEN * B_SZ * E_DIM];
__device__ float g_ao    [(size_t)S_LEN * B_SZ * E_DIM];
__device__ float g_hidden[(size_t)S_LEN * B_SZ * FF_DIM];
__device__ float g_z     [(size_t)S_LEN * B_SZ * E_DIM];

// ---------------- tf32 helpers ----------------------------------------------
__device__ __forceinline__ uint32_t to_tf32(float x) {
    uint32_t r;
    asm("cvt.rna.tf32.f32 %0, %1;" : "=r"(r) : "f"(x));
    return r;
}

// split x into hi (tf32) + lo (tf32 of residual)
__device__ __forceinline__ void tf32_split(float x, uint32_t& h, uint32_t& l) {
    h = to_tf32(x);
    l = to_tf32(x - __uint_as_float(h));
}

__device__ __forceinline__ void mma_tf32(float c[4], const uint32_t a[4],
                                         const uint32_t b[2]) {
    asm volatile(
        "mma.sync.aligned.m16n8k8.row.col.f32.tf32.tf32.f32 "
        "{%0,%1,%2,%3},{%4,%5,%6,%7},{%8,%9},{%0,%1,%2,%3};\n"
        : "+f"(c[0]), "+f"(c[1]), "+f"(c[2]), "+f"(c[3])
        : "r"(a[0]), "r"(a[1]), "r"(a[2]), "r"(a[3]), "r"(b[0]), "r"(b[1]));
}

// =============================================================================
// Dense GEMM: C(M,N) = gather(A)(M,Kd) @ B(Kd,N), 3xTF32.
// Block 128x128, BK=16, 8 warps (2x4), warp tile 64x32 (MT=4, NT=4).
// =============================================================================
template<int BIAS, int RELU>
__global__ __launch_bounds__(256)
void gemm_dense(const float* __restrict__ A0, const float* __restrict__ A1,
                int splitRow, const float* __restrict__ Bm,
                const float* __restrict__ bias, float* __restrict__ C,
                int N, int Kd)
{
    __shared__ uint32_t Ah[16][136], Al[16][136];
    __shared__ uint32_t Bh[16][136], Bl[16][136];

    const int tid = threadIdx.x, lane = tid & 31, warp = tid >> 5;
    const int bm = blockIdx.y * 128, bn = blockIdx.x * 128;
    const int wm = (warp >> 2) * 64, wn = (warp & 3) * 32;

    const int arow = tid >> 1;
    const int ak = (tid & 1) * 8;
    const int grow = bm + arow;
    const float* aP = (grow < splitRow)
        ? (A0 + (size_t)grow * Kd) : (A1 + (size_t)(grow - splitRow) * Kd);

    const int bk = tid >> 4;                 // 0..15
    const int bnc = (tid & 15) * 4;          // 0..60
    const float* bP = Bm + (size_t)bk * N + bn + bnc;

    float acc[16][4];
    #pragma unroll
    for (int t = 0; t < 16; t++) { acc[t][0]=acc[t][1]=acc[t][2]=acc[t][3]=0.f; }

    for (int k0 = 0; k0 < Kd; k0 += 16) {
        float4 av0 = *(const float4*)(aP + k0 + ak);
        float4 av1 = *(const float4*)(aP + k0 + ak + 4);
        tf32_split(av0.x, Ah[ak+0][arow], Al[ak+0][arow]);
        tf32_split(av0.y, Ah[ak+1][arow], Al[ak+1][arow]);
        tf32_split(av0.z, Ah[ak+2][arow], Al[ak+2][arow]);
        tf32_split(av0.w, Ah[ak+3][arow], Al[ak+3][arow]);
        tf32_split(av1.x, Ah[ak+4][arow], Al[ak+4][arow]);
        tf32_split(av1.y, Ah[ak+5][arow], Al[ak+5][arow]);
        tf32_split(av1.z, Ah[ak+6][arow], Al[ak+6][arow]);
        tf32_split(av1.w, Ah[ak+7][arow], Al[ak+7][arow]);

        float4 bv0 = *(const float4*)(bP + (size_t)k0 * N);
        float4 bv1 = *(const float4*)(bP + (size_t)k0 * N + 64);
        tf32_split(bv0.x, Bh[bk][bnc+0], Bl[bk][bnc+0]);
        tf32_split(bv0.y, Bh[bk][bnc+1], Bl[bk][bnc+1]);
        tf32_split(bv0.z, Bh[bk][bnc+2], Bl[bk][bnc+2]);
        tf32_split(bv0.w, Bh[bk][bnc+3], Bl[bk][bnc+3]);
        tf32_split(bv1.x, Bh[bk][bnc+64], Bl[bk][bnc+64]);
        tf32_split(bv1.y, Bh[bk][bnc+65], Bl[bk][bnc+65]);
        tf32_split(bv1.z, Bh[bk][bnc+66], Bl[bk][bnc+66]);
        tf32_split(bv1.w, Bh[bk][bnc+67], Bl[bk][bnc+67]);
        __syncthreads();

        #pragma unroll
        for (int kk = 0; kk < 2; kk++) {
            const int kb = kk * 8 + (lane & 3);
            const int lm = lane >> 2;
            uint32_t bh[4][2], bl[4][2];
            #pragma unroll
            for (int nt = 0; nt < 4; nt++) {
                const int n0 = wn + nt * 8 + lm;
                bh[nt][0] = Bh[kb][n0];     bh[nt][1] = Bh[kb+4][n0];
                bl[nt][0] = Bl[kb][n0];     bl[nt][1] = Bl[kb+4][n0];
            }
            #pragma unroll
            for (int mt = 0; mt < 4; mt++) {
                const int m0 = wm + mt * 16 + lm;
                uint32_t ah[4], al[4];
                ah[0] = Ah[kb][m0];     ah[1] = Ah[kb][m0+8];
                ah[2] = Ah[kb+4][m0];   ah[3] = Ah[kb+4][m0+8];
                al[0] = Al[kb][m0];     al[1] = Al[kb][m0+8];
                al[2] = Al[kb+4][m0];   al[3] = Al[kb+4][m0+8];
                #pragma unroll
                for (int nt = 0; nt < 4; nt++) {
                    mma_tf32(acc[mt*4+nt], al, bh[nt]);
                    mma_tf32(acc[mt*4+nt], ah, bl[nt]);
                    mma_tf32(acc[mt*4+nt], ah, bh[nt]);
                }
            }
        }
        __syncthreads();
    }

    #pragma unroll
    for (int mt = 0; mt < 4; mt++) {
        #pragma unroll
        for (int nt = 0; nt < 4; nt++) {
            const int row = bm + wm + mt*16 + (lane >> 2);
            const int col = bn + wn + nt*8 + (lane & 3) * 2;
            const float* ap = acc[mt*4+nt];
            float v0 = ap[0], v1 = ap[1], v2 = ap[2], v3 = ap[3];
            if (BIAS) {
                const float b0 = bias[col], b1 = bias[col+1];
                v0 += b0; v1 += b1; v2 += b0; v3 += b1;
            }
            if (RELU) {
                v0 = fmaxf(v0, 0.f); v1 = fmaxf(v1, 0.f);
                v2 = fmaxf(v2, 0.f); v3 = fmaxf(v3, 0.f);
            }
            float* cp = C + (size_t)row * N + col;
            cp[0] = v0; cp[1] = v1;
            cp[(size_t)8 * N] = v2; cp[(size_t)8 * N + 1] = v3;
        }
    }
}

// =============================================================================
// Score GEMMs, 3xTF32.
//   IS_BD=0: score[z][i][j] = sum_d (q[i,d]+u[d]) * k[j,d]      (plain store)
//   IS_BD=1: Bt[i][jj] = sum_d (q[i,d]+v[d]) * r[jj,d]; epilogue applies the
//            rel-shift inline: score[z][i][jj-(S-1-i)] += Bt  (when idx >= 0).
// Kd = 64. Tile-skip from causal/rel-shift structure.
// =============================================================================
template<int IS_BD>
__global__ __launch_bounds__(256)
void gemm_score(const float* __restrict__ uv)
{
    const int j0 = blockIdx.x * 128;
    const int i0 = blockIdx.y * 128;
    if (!IS_BD && j0 > i0 + 127 + M_MEM) return;       // fully masked
    if (IS_BD && (i0 + j0 < S_LEN - 255)) return;      // shift target < 0 always
    const int z = blockIdx.z;
    const int b = z >> 3, h = z & 7;

    __shared__ uint32_t Ah[16][136], Al[16][136];
    __shared__ uint32_t Bh[16][136], Bl[16][136];

    const int tid = threadIdx.x, lane = tid & 31, warp = tid >> 5;
    const int wm = (warp >> 2) * 64, wn = (warp & 3) * 32;

    const int row = tid >> 1;            // 0..127 (for both A and B tiles)
    const int dk = (tid & 1) * 8;        // 0 or 8

    const float* aP = g_qkv
        + ((size_t)(M_MEM + i0 + row) * B_SZ + b) * QKV3 + h * I_DIM + dk;
    const float* uvP = uv + h * I_DIM + dk;
    const float* bP = IS_BD
        ? (g_r + (size_t)(j0 + row) * HI + h * I_DIM + dk)
        : (g_qkv + ((size_t)(j0 + row) * B_SZ + b) * QKV3 + HI + h * I_DIM + dk);

    float acc[16][4];
    #pragma unroll
    for (int t = 0; t < 16; t++) { acc[t][0]=acc[t][1]=acc[t][2]=acc[t][3]=0.f; }

    for (int k0 = 0; k0 < I_DIM; k0 += 16) {
        float4 av0 = *(const float4*)(aP + k0);
        float4 av1 = *(const float4*)(aP + k0 + 4);
        float4 uv0 = *(const float4*)(uvP + k0);
        float4 uv1 = *(const float4*)(uvP + k0 + 4);
        tf32_split(av0.x + uv0.x, Ah[dk+0][row], Al[dk+0][row]);
        tf32_split(av0.y + uv0.y, Ah[dk+1][row], Al[dk+1][row]);
        tf32_split(av0.z + uv0.z, Ah[dk+2][row], Al[dk+2][row]);
        tf32_split(av0.w + uv0.w, Ah[dk+3][row], Al[dk+3][row]);
        tf32_split(av1.x + uv1.x, Ah[dk+4][row], Al[dk+4][row]);
        tf32_split(av1.y + uv1.y, Ah[dk+5][row], Al[dk+5][row]);
        tf32_split(av1.z + uv1.z, Ah[dk+6][row], Al[dk+6][row]);
        tf32_split(av1.w + uv1.w, Ah[dk+7][row], Al[dk+7][row]);

        float4 bv0 = *(const float4*)(bP + k0);
        float4 bv1 = *(const float4*)(bP + k0 + 4);
        tf32_split(bv0.x, Bh[dk+0][row], Bl[dk+0][row]);
        tf32_split(bv0.y, Bh[dk+1][row], Bl[dk+1][row]);
        tf32_split(bv0.z, Bh[dk+2][row], Bl[dk+2][row]);
        tf32_split(bv0.w, Bh[dk+3][row], Bl[dk+3][row]);
        tf32_split(bv1.x, Bh[dk+4][row], Bl[dk+4][row]);
        tf32_split(bv1.y, Bh[dk+5][row], Bl[dk+5][row]);
        tf32_split(bv1.z, Bh[dk+6][row], Bl[dk+6][row]);
        tf32_split(bv1.w, Bh[dk+7][row], Bl[dk+7][row]);
        __syncthreads();

        #pragma unroll
        for (int kk = 0; kk < 2; kk++) {
            const int kb = kk * 8 + (lane & 3);
            const int lm = lane >> 2;
            uint32_t bh[4][2], bl[4][2];
            #pragma unroll
            for (int nt = 0; nt < 4; nt++) {
                const int n0 = wn + nt * 8 + lm;
                bh[nt][0] = Bh[kb][n0];   bh[nt][1] = Bh[kb+4][n0];
                bl[nt][0] = Bl[kb][n0];   bl[nt][1] = Bl[kb+4][n0];
            }
            #pragma unroll
            for (int mt = 0; mt < 4; mt++) {
                const int m0 = wm + mt * 16 + lm;
                uint32_t ah[4], al[4];
                ah[0] = Ah[kb][m0];     ah[1] = Ah[kb][m0+8];
                ah[2] = Ah[kb+4][m0];   ah[3] = Ah[kb+4][m0+8];
                al[0] = Al[kb][m0];     al[1] = Al[kb][m0+8];
                al[2] = Al[kb+4][m0];   al[3] = Al[kb+4][m0+8];
                #pragma unroll
                for (int nt = 0; nt < 4; nt++) {
                    mma_tf32(acc[mt*4+nt], al, bh[nt]);
                    mma_tf32(acc[mt*4+nt], ah, bl[nt]);
                    mma_tf32(acc[mt*4+nt], ah, bh[nt]);
                }
            }
        }
        __syncthreads();
    }

    float* Cbase = g_score + (size_t)z * S_LEN * K_LEN;
    #pragma unroll
    for (int mt = 0; mt < 4; mt++) {
        #pragma unroll
        for (int nt = 0; nt < 4; nt++) {
            const int r0 = i0 + wm + mt*16 + (lane >> 2);
            const int c0 = j0 + wn + nt*8 + (lane & 3) * 2;
            if (!IS_BD) {
                float* cp = Cbase + (size_t)r0 * K_LEN + c0;
                cp[0] = acc[mt*4+nt][0]; cp[1] = acc[mt*4+nt][1];
                cp[(size_t)8 * K_LEN] = acc[mt*4+nt][2];
                cp[(size_t)8 * K_LEN + 1] = acc[mt*4+nt][3];
            } else {
                // rel-shift: score[i][jj - (S-1-i)] += Bt[i][jj]
                const int sh0 = c0 - (S_LEN - 1 - r0);         // j for row r0
                const int sh1 = c0 - (S_LEN - 1 - (r0 + 8));   // j for row r0+8
                float* cp0 = Cbase + (size_t)r0 * K_LEN + sh0;
                float* cp1 = Cbase + (size_t)(r0 + 8) * K_LEN + sh1;
                if (sh0 >= 0)     cp0[0] += acc[mt*4+nt][0];
                if (sh0 + 1 >= 0) cp0[1] += acc[mt*4+nt][1];
                if (sh1 >= 0)     cp1[0] += acc[mt*4+nt][2];
                if (sh1 + 1 >= 0) cp1[1] += acc[mt*4+nt][3];
            }
        }
    }
}

// =============================================================================
// Softmax: logits = score[i,j] / 8 over j in [0, i+m]; zero the masked tail.
// Register-stashed logits: 1 read + 1 write of the row.
// =============================================================================
__global__ __launch_bounds__(256)
void softmax_kernel()
{
    const int rowid = blockIdx.x;              // z*S + i
    const int i = rowid & (S_LEN - 1);
    float* p = g_score + (size_t)rowid * K_LEN;
    const int jmax = i + M_MEM + 1;
    const int tid = threadIdx.x;
    __shared__ float red[256];

    float l[16];
    float mx = -1e30f;
    #pragma unroll
    for (int t = 0; t < 16; t++) {
        const int j = tid + t * 256;
        if (j < jmax) {
            const float v = p[j] * 0.125f;
            l[t] = v;
            mx = fmaxf(mx, v);
        }
    }
    red[tid] = mx; __syncthreads();
    for (int s = 128; s > 0; s >>= 1) {
        if (tid < s) red[tid] = fmaxf(red[tid], red[tid + s]);
        __syncthreads();
    }
    mx = red[0]; __syncthreads();

    float sum = 0.f;
    #pragma unroll
    for (int t = 0; t < 16; t++) {
        const int j = tid + t * 256;
        if (j < jmax) {
            const float e = __expf(l[t] - mx);
            l[t] = e;
            sum += e;
        }
    }
    red[tid] = sum; __syncthreads();
    for (int s = 128; s > 0; s >>= 1) {
        if (tid < s) red[tid] += red[tid + s];
        __syncthreads();
    }
    const float inv = 1.f / red[0];

    #pragma unroll
    for (int t = 0; t < 16; t++) {
        const int j = tid + t * 256;
        if (j < jmax) p[j] = l[t] * inv;
    }
    for (int j = jmax + tid; j < K_LEN; j += 256) p[j] = 0.f;
}

// =============================================================================
// attn = P @ V per z, 3xTF32. BM=128 (i), BN=64 (d), banded k (keys).
// 8 warps 2x4, warp tile 64x16: MT=4, NT=2.
// =============================================================================
__global__ __launch_bounds__(256)
void gemm_attnv()
{
    const int i0 = blockIdx.x * 128;
    const int z = blockIdx.y;
    const int b = z >> 3, h = z & 7;
    const int kmax = i0 + 127 + M_MEM + 1;     // multiple of 16

    __shared__ uint32_t Ah[16][136], Al[16][136];
    __shared__ uint32_t Bh[16][72],  Bl[16][72];

    const int tid = threadIdx.x, lane = tid & 31, warp = tid >> 5;
    const int wm = (warp >> 2) * 64, wn = (warp & 3) * 16;

    const int arow = tid >> 1;           // i within tile
    const int ajk = (tid & 1) * 8;
    const float* aP = g_score + ((size_t)z * S_LEN + i0 + arow) * K_LEN + ajk;

    const int bk = tid >> 4;             // 0..15 (key within k-tile)
    const int bnc = (tid & 15) * 4;      // 0..60 (d)
    const float* bP = g_qkv + ((size_t)bk * B_SZ + b) * QKV3 + 2 * HI
                    + h * I_DIM + bnc;

    float acc[8][4];
    #pragma unroll
    for (int t = 0; t < 8; t++) { acc[t][0]=acc[t][1]=acc[t][2]=acc[t][3]=0.f; }

    for (int k0 = 0; k0 < kmax; k0 += 16) {
        float4 av0 = *(const float4*)(aP + k0);
        float4 av1 = *(const float4*)(aP + k0 + 4);
        tf32_split(av0.x, Ah[ajk+0][arow], Al[ajk+0][arow]);
        tf32_split(av0.y, Ah[ajk+1][arow], Al[ajk+1][arow]);
        tf32_split(av0.z, Ah[ajk+2][arow], Al[ajk+2][arow]);
        tf32_split(av0.w, Ah[ajk+3][arow], Al[ajk+3][arow]);
        tf32_split(av1.x, Ah[ajk+4][arow], Al[ajk+4][arow]);
        tf32_split(av1.y, Ah[ajk+5][arow], Al[ajk+5][arow]);
        tf32_split(av1.z, Ah[ajk+6][arow], Al[ajk+6][arow]);
        tf32_split(av1.w, Ah[ajk+7][arow], Al[ajk+7][arow]);

        float4 bv = *(const float4*)(bP + (size_t)k0 * B_SZ * QKV3);
        tf32_split(bv.x, Bh[bk][bnc+0], Bl[bk][bnc+0]);
        tf32_split(bv.y, Bh[bk][bnc+1], Bl[bk][bnc+1]);
        tf32_split(bv.z, Bh[bk][bnc+2], Bl[bk][bnc+2]);
        tf32_split(bv.w, Bh[bk][bnc+3], Bl[bk][bnc+3]);
        __syncthreads();

        #pragma unroll
        for (int kk = 0; kk < 2; kk++) {
            const int kb = kk * 8 + (lane & 3);
            const int lm = lane >> 2;
            uint32_t bh[2][2], bl[2][2];
            #pragma unroll
            for (int nt = 0; nt < 2; nt++) {
                const int n0 = wn + nt * 8 + lm;
                bh[nt][0] = Bh[kb][n0];   bh[nt][1] = Bh[kb+4][n0];
                bl[nt][0] = Bl[kb][n0];   bl[nt][1] = Bl[kb+4][n0];
            }
            #pragma unroll
            for (int mt = 0; mt < 4; mt++) {
                const int m0 = wm + mt * 16 + lm;
                uint32_t ah[4], al[4];
                ah[0] = Ah[kb][m0];     ah[1] = Ah[kb][m0+8];
                ah[2] = Ah[kb+4][m0];   ah[3] = Ah[kb+4][m0+8];
                al[0] = Al[kb][m0];     al[1] = Al[kb][m0+8];
                al[2] = Al[kb+4][m0];   al[3] = Al[kb+4][m0+8];
                #pragma unroll
                for (int nt = 0; nt < 2; nt++) {
                    mma_tf32(acc[mt*2+nt], al, bh[nt]);
                    mma_tf32(acc[mt*2+nt], ah, bl[nt]);
                    mma_tf32(acc[mt*2+nt], ah, bh[nt]);
                }
            }
        }
        __syncthreads();
    }

    #pragma unroll
    for (int mt = 0; mt < 4; mt++) {
        #pragma unroll
        for (int nt = 0; nt < 2; nt++) {
            const int i = i0 + wm + mt*16 + (lane >> 2);
            const int d = wn + nt*8 + (lane & 3) * 2;
            float* cp = g_attn + ((size_t)i * B_SZ + b) * E_DIM + h * I_DIM + d;
            cp[0] = acc[mt*2+nt][0]; cp[1] = acc[mt*2+nt][1];
            float* cp2 = g_attn + ((size_t)(i+8) * B_SZ + b) * E_DIM + h * I_DIM + d;
            cp2[0] = acc[mt*2+nt][2]; cp2[1] = acc[mt*2+nt][3];
        }
    }
}

// ---------------- residual (+optional extra bias) + LayerNorm ----------------
__global__ __launch_bounds__(256)
void ln_kernel(const float* __restrict__ x1, const float* __restrict__ x2,
               const float* __restrict__ extra_bias,
               const float* __restrict__ gamma, const float* __restrict__ beta,
               float* __restrict__ out)
{
    const int row = blockIdx.x;
    const int tid = threadIdx.x;
    const float* p1 = x1 + (size_t)row * E_DIM;
    const float* p2 = x2 + (size_t)row * E_DIM;
    float v0 = p1[tid] + p2[tid];
    float v1 = p1[tid + 256] + p2[tid + 256];
    if (extra_bias) { v0 += extra_bias[tid]; v1 += extra_bias[tid + 256]; }

    __shared__ float red[256];
    red[tid] = v0 + v1; __syncthreads();
    for (int s = 128; s > 0; s >>= 1) {
        if (tid < s) red[tid] += red[tid + s];
        __syncthreads();
    }
    const float mean = red[0] * (1.f / E_DIM);
    __syncthreads();
    const float d0 = v0 - mean, d1 = v1 - mean;
    red[tid] = d0 * d0 + d1 * d1; __syncthreads();
    for (int s = 128; s > 0; s >>= 1) {
        if (tid < s) red[tid] += red[tid + s];
        __syncthreads();
    }
    const float rstd = rsqrtf(red[0] * (1.f / E_DIM) + 1e-5f);
    out[(size_t)row * E_DIM + tid]       = d0 * rstd * gamma[tid]       + beta[tid];
    out[(size_t)row * E_DIM + tid + 256] = d1 * rstd * gamma[tid + 256] + beta[tid + 256];
}

// ---------------- launch ------------------------------------------------------
extern "C" void kernel_launch(void* const* d_in, const int* in_sizes, int n_in,
                              void* d_out, int out_size)
{
    const float* inputDec = (const float*)d_in[0];
    const float* posEmb   = (const float*)d_in[1];
    const float* u        = (const float*)d_in[2];
    const float* v        = (const float*)d_in[3];
    const float* memories = (const float*)d_in[4];
    const float* Wqkv     = (const float*)d_in[5];
    const float* Wr       = (const float*)d_in[6];
    const float* Wo       = (const float*)d_in[7];
    const float* ln1_g    = (const float*)d_in[8];
    const float* ln1_b    = (const float*)d_in[9];
    const float* W1       = (const float*)d_in[10];
    const float* b1       = (const float*)d_in[11];
    const float* W2       = (const float*)d_in[12];
    const float* b2       = (const float*)d_in[13];
    const float* ln2_g    = (const float*)d_in[14];
    const float* ln2_b    = (const float*)d_in[15];
    float* out = (float*)d_out;

    float *p_qkv, *p_r, *p_attn, *p_y, *p_ao, *p_h, *p_z;
    cudaGetSymbolAddress((void**)&p_qkv, g_qkv);
    cudaGetSymbolAddress((void**)&p_r, g_r);
    cudaGetSymbolAddress((void**)&p_attn, g_attn);
    cudaGetSymbolAddress((void**)&p_y, g_y);
    cudaGetSymbolAddress((void**)&p_ao, g_ao);
    cudaGetSymbolAddress((void**)&p_h, g_hidden);
    cudaGetSymbolAddress((void**)&p_z, g_z);

    // 1) qkv = concat(memories, inputDec) @ Wqkv     (8192 x 1536 x 512)
    gemm_dense<0,0><<<dim3(QKV3 / 128, (K_LEN * B_SZ) / 128), 256>>>(
        memories, inputDec, M_MEM * B_SZ, Wqkv, nullptr, p_qkv, QKV3, E_DIM);

    // 2) r = posEmbeddings @ Wr                      (4096 x 512 x 512)
    gemm_dense<0,0><<<dim3(HI / 128, K_LEN / 128), 256>>>(
        posEmb, posEmb, K_LEN, Wr, nullptr, p_r, HI, E_DIM);

    // 3) AC score GEMM (stores), then BD GEMM (rel-shift add in epilogue)
    gemm_score<0><<<dim3(K_LEN / 128, S_LEN / 128, B_SZ * H_HEADS), 256>>>(u);
    gemm_score<1><<<dim3(K_LEN / 128, S_LEN / 128, B_SZ * H_HEADS), 256>>>(v);

    // 4) softmax
    softmax_kernel<<<B_SZ * H_HEADS * S_LEN, 256>>>();

    // 5) attn = P @ V
    gemm_attnv<<<dim3(S_LEN / 128, B_SZ * H_HEADS), 256>>>();

    // 6) y = attn @ Wo                               (4096 x 512 x 512)
    gemm_dense<0,0><<<dim3(E_DIM / 128, (S_LEN * B_SZ) / 128), 256>>>(
        p_attn, p_attn, S_LEN * B_SZ, Wo, nullptr, p_y, E_DIM, HI);

    // 7) attn_out = LN(inputDec + y)
    ln_kernel<<<S_LEN * B_SZ, 256>>>(inputDec, p_y, nullptr, ln1_g, ln1_b, p_ao);

    // 8) hidden = relu(attn_out @ W1 + b1)           (4096 x 2048 x 512)
    gemm_dense<1,1><<<dim3(FF_DIM / 128, (S_LEN * B_SZ) / 128), 256>>>(
        p_ao, p_ao, S_LEN * B_SZ, W1, b1, p_h, FF_DIM, E_DIM);

    // 9) z = hidden @ W2                             (4096 x 512 x 2048)
    gemm_dense<0,0><<<dim3(E_DIM / 128, (S_LEN * B_SZ) / 128), 256>>>(
        p_h, p_h, S_LEN * B_SZ, W2, nullptr, p_z, E_DIM, FF_DIM);

    // 10) out = LN(attn_out + z + b2)
    ln_kernel<<<S_LEN * B_SZ, 256>>>(p_ao, p_z, b2, ln2_g, ln2_b, out);
}

// round 6
// speedup vs baseline: 2.1919x; 1.3170x over previous
#include <cuda_runtime.h>
#include <cuda_bf16.h>
#include <cstdint>
#include <cstddef>

#define S_LEN   2048
#define B_SZ    2
#define E_DIM   512
#define H_HEADS 8
#define I_DIM   64
#define M_MEM   2048
#define FF_DIM  2048
#define K_LEN   (M_MEM + S_LEN)      // 4096
#define HI      (H_HEADS * I_DIM)    // 512
#define QKV3    (3 * HI)             // 1536

// ---------------- scratch (device globals; no allocations allowed) ----------
__device__ float g_qkv   [(size_t)K_LEN * B_SZ * QKV3];            // 50 MB
__device__ float g_r     [(size_t)K_LEN * HI];                     //  8 MB
__device__ float g_score [(size_t)B_SZ * H_HEADS * S_LEN * K_LEN]; // 536 MB
__device__ float g_attn  [(size_t)S_LEN * B_SZ * E_DIM];
__device__ float g_y     [(size_t)S_LEN * B_SZ * E_DIM];
__device__ float g_ao    [(size_t)S_LEN * B_SZ * E_DIM];
__device__ float g_hidden[(size_t)S_LEN * B_SZ * FF_DIM];
__device__ float g_z     [(size_t)S_LEN * B_SZ * E_DIM];

// ---------------- bf16 split helpers -----------------------------------------
// Pack (x0, x1) into one bf16x2 word for hi and one for lo (residual).
__device__ __forceinline__ void bf16_split2(float x0, float x1,
                                            uint32_t& hi, uint32_t& lo) {
    __nv_bfloat162 h = __floats2bfloat162_rn(x0, x1);
    float r0 = x0 - __low2float(h);
    float r1 = x1 - __high2float(h);
    __nv_bfloat162 l = __floats2bfloat162_rn(r0, r1);
    hi = *reinterpret_cast<uint32_t*>(&h);
    lo = *reinterpret_cast<uint32_t*>(&l);
}

__device__ __forceinline__ void mma_bf16(float c[4], const uint32_t a[4],
                                         const uint32_t b[2]) {
    asm volatile(
        "mma.sync.aligned.m16n8k16.row.col.f32.bf16.bf16.f32 "
        "{%0,%1,%2,%3},{%4,%5,%6,%7},{%8,%9},{%0,%1,%2,%3};\n"
        : "+f"(c[0]), "+f"(c[1]), "+f"(c[2]), "+f"(c[3])
        : "r"(a[0]), "r"(a[1]), "r"(a[2]), "r"(a[3]), "r"(b[0]), "r"(b[1]));
}

// smem layout: X[pair][item] with stride 136 words. 136 % 32 == 8, so the
// fragment access pattern addr = pair*136 + item with pair = lane&3 (+4) and
// item = ... + (lane>>2) maps to banks 8*(lane&3) + (lane>>2): conflict-free.

// =============================================================================
// Dense GEMM: C(M,N) = gather(A)(M,Kd) @ B(Kd,N), 3xBF16 (hi/lo split).
// Block 128x128, BK=16, 8 warps (2x4), warp tile 64x32 (MT=4, NT=4).
// =============================================================================
template<int BIAS, int RELU>
__global__ __launch_bounds__(256)
void gemm_dense(const float* __restrict__ A0, const float* __restrict__ A1,
                int splitRow, const float* __restrict__ Bm,
                const float* __restrict__ bias, float* __restrict__ C,
                int N, int Kd)
{
    __shared__ uint32_t Ah[8][136], Al[8][136];
    __shared__ uint32_t Bh[8][136], Bl[8][136];

    const int tid = threadIdx.x, lane = tid & 31, warp = tid >> 5;
    const int bm = blockIdx.y * 128, bn = blockIdx.x * 128;
    const int wm = (warp >> 2) * 64, wn = (warp & 3) * 32;

    const int arow = tid >> 1;           // 0..127
    const int ak = (tid & 1) * 8;        // 0 or 8 (k offset)
    const int ap0 = ak >> 1;             // pair base: 0 or 4
    const int grow = bm + arow;
    const float* aP = (grow < splitRow)
        ? (A0 + (size_t)grow * Kd) : (A1 + (size_t)(grow - splitRow) * Kd);

    const int bpr = warp;                // B k-pair row 0..7
    const int bn4 = lane * 4;            // 0..124
    const float* bP = Bm + (size_t)(2 * bpr) * N + bn + bn4;

    const int pa = lane & 3, lm = lane >> 2;

    float acc[16][4];
    #pragma unroll
    for (int t = 0; t < 16; t++) { acc[t][0]=acc[t][1]=acc[t][2]=acc[t][3]=0.f; }

    for (int k0 = 0; k0 < Kd; k0 += 16) {
        // ---- A convert: row arow, ks [k0+ak, k0+ak+8) -> pairs ap0..ap0+3
        float4 av0 = *(const float4*)(aP + k0 + ak);
        float4 av1 = *(const float4*)(aP + k0 + ak + 4);
        bf16_split2(av0.x, av0.y, Ah[ap0+0][arow], Al[ap0+0][arow]);
        bf16_split2(av0.z, av0.w, Ah[ap0+1][arow], Al[ap0+1][arow]);
        bf16_split2(av1.x, av1.y, Ah[ap0+2][arow], Al[ap0+2][arow]);
        bf16_split2(av1.z, av1.w, Ah[ap0+3][arow], Al[ap0+3][arow]);

        // ---- B convert: k rows (k0+2bpr, k0+2bpr+1), cols bn4..bn4+3
        const float* b0p = bP + (size_t)k0 * N;
        float4 b0 = *(const float4*)b0p;
        float4 b1 = *(const float4*)(b0p + N);
        uint32_t h0,l0,h1,l1,h2,l2,h3,l3;
        bf16_split2(b0.x, b1.x, h0, l0);
        bf16_split2(b0.y, b1.y, h1, l1);
        bf16_split2(b0.z, b1.z, h2, l2);
        bf16_split2(b0.w, b1.w, h3, l3);
        *(uint4*)&Bh[bpr][bn4] = make_uint4(h0, h1, h2, h3);
        *(uint4*)&Bl[bpr][bn4] = make_uint4(l0, l1, l2, l3);
        __syncthreads();

        uint32_t bhf[4][2], blf[4][2];
        #pragma unroll
        for (int nt = 0; nt < 4; nt++) {
            const int n0 = wn + nt * 8 + lm;
            bhf[nt][0] = Bh[pa][n0];     bhf[nt][1] = Bh[pa+4][n0];
            blf[nt][0] = Bl[pa][n0];     blf[nt][1] = Bl[pa+4][n0];
        }
        #pragma unroll
        for (int mt = 0; mt < 4; mt++) {
            const int m0 = wm + mt * 16 + lm;
            uint32_t ah[4], al[4];
            ah[0] = Ah[pa][m0];    ah[1] = Ah[pa][m0+8];
            ah[2] = Ah[pa+4][m0];  ah[3] = Ah[pa+4][m0+8];
            al[0] = Al[pa][m0];    al[1] = Al[pa][m0+8];
            al[2] = Al[pa+4][m0];  al[3] = Al[pa+4][m0+8];
            #pragma unroll
            for (int nt = 0; nt < 4; nt++) {
                mma_bf16(acc[mt*4+nt], al, bhf[nt]);
                mma_bf16(acc[mt*4+nt], ah, blf[nt]);
                mma_bf16(acc[mt*4+nt], ah, bhf[nt]);
            }
        }
        __syncthreads();
    }

    #pragma unroll
    for (int mt = 0; mt < 4; mt++) {
        #pragma unroll
        for (int nt = 0; nt < 4; nt++) {
            const int row = bm + wm + mt*16 + lm;
            const int col = bn + wn + nt*8 + pa * 2;
            const float* ap = acc[mt*4+nt];
            float v0 = ap[0], v1 = ap[1], v2 = ap[2], v3 = ap[3];
            if (BIAS) {
                const float bb0 = bias[col], bb1 = bias[col+1];
                v0 += bb0; v1 += bb1; v2 += bb0; v3 += bb1;
            }
            if (RELU) {
                v0 = fmaxf(v0, 0.f); v1 = fmaxf(v1, 0.f);
                v2 = fmaxf(v2, 0.f); v3 = fmaxf(v3, 0.f);
            }
            float* cp = C + (size_t)row * N + col;
            cp[0] = v0; cp[1] = v1;
            cp[(size_t)8 * N] = v2; cp[(size_t)8 * N + 1] = v3;
        }
    }
}

// =============================================================================
// Score GEMMs, 3xBF16.
//   IS_BD=0: score[z][i][j] = sum_d (q[i,d]+u[d]) * k[j,d]      (plain store)
//   IS_BD=1: Bt[i][jj] = sum_d (q[i,d]+v[d]) * r[jj,d]; epilogue applies the
//            rel-shift inline: score[z][i][jj-(S-1-i)] += Bt  (when idx >= 0).
// Kd = 64. Both operand tiles are [row][d] — A-style conversion for both.
// =============================================================================
template<int IS_BD>
__global__ __launch_bounds__(256)
void gemm_score(const float* __restrict__ uv)
{
    const int j0 = blockIdx.x * 128;
    const int i0 = blockIdx.y * 128;
    if (!IS_BD && j0 > i0 + 127 + M_MEM) return;       // fully masked
    if (IS_BD && (i0 + j0 < S_LEN - 255)) return;      // shift target < 0 always
    const int z = blockIdx.z;
    const int b = z >> 3, h = z & 7;

    __shared__ uint32_t Ah[8][136], Al[8][136];
    __shared__ uint32_t Bh[8][136], Bl[8][136];

    const int tid = threadIdx.x, lane = tid & 31, warp = tid >> 5;
    const int wm = (warp >> 2) * 64, wn = (warp & 3) * 32;

    const int row = tid >> 1;            // 0..127 (both A and B tiles)
    const int dk = (tid & 1) * 8;        // 0 or 8
    const int ap0 = dk >> 1;             // pair base 0 or 4
    const int pa = lane & 3, lm = lane >> 2;

    const float* aP = g_qkv
        + ((size_t)(M_MEM + i0 + row) * B_SZ + b) * QKV3 + h * I_DIM + dk;
    const float* uvP = uv + h * I_DIM + dk;
    const float* bP = IS_BD
        ? (g_r + (size_t)(j0 + row) * HI + h * I_DIM + dk)
        : (g_qkv + ((size_t)(j0 + row) * B_SZ + b) * QKV3 + HI + h * I_DIM + dk);

    float acc[16][4];
    #pragma unroll
    for (int t = 0; t < 16; t++) { acc[t][0]=acc[t][1]=acc[t][2]=acc[t][3]=0.f; }

    for (int k0 = 0; k0 < I_DIM; k0 += 16) {
        float4 av0 = *(const float4*)(aP + k0);
        float4 av1 = *(const float4*)(aP + k0 + 4);
        float4 uv0 = *(const float4*)(uvP + k0);
        float4 uv1 = *(const float4*)(uvP + k0 + 4);
        bf16_split2(av0.x + uv0.x, av0.y + uv0.y, Ah[ap0+0][row], Al[ap0+0][row]);
        bf16_split2(av0.z + uv0.z, av0.w + uv0.w, Ah[ap0+1][row], Al[ap0+1][row]);
        bf16_split2(av1.x + uv1.x, av1.y + uv1.y, Ah[ap0+2][row], Al[ap0+2][row]);
        bf16_split2(av1.z + uv1.z, av1.w + uv1.w, Ah[ap0+3][row], Al[ap0+3][row]);

        float4 bv0 = *(const float4*)(bP + k0);
        float4 bv1 = *(const float4*)(bP + k0 + 4);
        bf16_split2(bv0.x, bv0.y, Bh[ap0+0][row], Bl[ap0+0][row]);
        bf16_split2(bv0.z, bv0.w, Bh[ap0+1][row], Bl[ap0+1][row]);
        bf16_split2(bv1.x, bv1.y, Bh[ap0+2][row], Bl[ap0+2][row]);
        bf16_split2(bv1.z, bv1.w, Bh[ap0+3][row], Bl[ap0+3][row]);
        __syncthreads();

        uint32_t bhf[4][2], blf[4][2];
        #pragma unroll
        for (int nt = 0; nt < 4; nt++) {
            const int n0 = wn + nt * 8 + lm;
            bhf[nt][0] = Bh[pa][n0];     bhf[nt][1] = Bh[pa+4][n0];
            blf[nt][0] = Bl[pa][n0];     blf[nt][1] = Bl[pa+4][n0];
        }
        #pragma unroll
        for (int mt = 0; mt < 4; mt++) {
            const int m0 = wm + mt * 16 + lm;
            uint32_t ah[4], al[4];
            ah[0] = Ah[pa][m0];    ah[1] = Ah[pa][m0+8];
            ah[2] = Ah[pa+4][m0];  ah[3] = Ah[pa+4][m0+8];
            al[0] = Al[pa][m0];    al[1] = Al[pa][m0+8];
            al[2] = Al[pa+4][m0];  al[3] = Al[pa+4][m0+8];
            #pragma unroll
            for (int nt = 0; nt < 4; nt++) {
                mma_bf16(acc[mt*4+nt], al, bhf[nt]);
                mma_bf16(acc[mt*4+nt], ah, blf[nt]);
                mma_bf16(acc[mt*4+nt], ah, bhf[nt]);
            }
        }
        __syncthreads();
    }

    float* Cbase = g_score + (size_t)z * S_LEN * K_LEN;
    #pragma unroll
    for (int mt = 0; mt < 4; mt++) {
        #pragma unroll
        for (int nt = 0; nt < 4; nt++) {
            const int r0 = i0 + wm + mt*16 + lm;
            const int c0 = j0 + wn + nt*8 + pa * 2;
            if (!IS_BD) {
                float* cp = Cbase + (size_t)r0 * K_LEN + c0;
                cp[0] = acc[mt*4+nt][0]; cp[1] = acc[mt*4+nt][1];
                cp[(size_t)8 * K_LEN] = acc[mt*4+nt][2];
                cp[(size_t)8 * K_LEN + 1] = acc[mt*4+nt][3];
            } else {
                // rel-shift: score[i][jj - (S-1-i)] += Bt[i][jj]
                const int sh0 = c0 - (S_LEN - 1 - r0);         // j for row r0
                const int sh1 = c0 - (S_LEN - 1 - (r0 + 8));   // j for row r0+8
                float* cp0 = Cbase + (size_t)r0 * K_LEN + sh0;
                float* cp1 = Cbase + (size_t)(r0 + 8) * K_LEN + sh1;
                if (sh0 >= 0)     cp0[0] += acc[mt*4+nt][0];
                if (sh0 + 1 >= 0) cp0[1] += acc[mt*4+nt][1];
                if (sh1 >= 0)     cp1[0] += acc[mt*4+nt][2];
                if (sh1 + 1 >= 0) cp1[1] += acc[mt*4+nt][3];
            }
        }
    }
}

// =============================================================================
// Softmax: logits = score[i,j] / 8 over j in [0, i+m]; zero the masked tail.
// float4-vectorized, register-stashed: 1 read + 1 write of the row.
// =============================================================================
__global__ __launch_bounds__(256)
void softmax_kernel()
{
    const int rowid = blockIdx.x;              // z*S + i
    const int i = rowid & (S_LEN - 1);
    float* p = g_score + (size_t)rowid * K_LEN;
    const int jmax = i + M_MEM + 1;
    const int full4 = jmax >> 2;               // complete float4s
    const int tid = threadIdx.x;
    __shared__ float red[256];

    float l[16];
    float mx = -1e30f;
    #pragma unroll
    for (int t = 0; t < 4; t++) {
        const int q = tid + t * 256;           // float4 index, 0..1023
        if (q < full4) {
            float4 x = ((const float4*)p)[q];
            l[t*4+0] = x.x * 0.125f; l[t*4+1] = x.y * 0.125f;
            l[t*4+2] = x.z * 0.125f; l[t*4+3] = x.w * 0.125f;
            mx = fmaxf(mx, fmaxf(fmaxf(l[t*4+0], l[t*4+1]),
                                 fmaxf(l[t*4+2], l[t*4+3])));
        } else {
            #pragma unroll
            for (int e = 0; e < 4; e++) {
                const int j = q * 4 + e;
                if (j < jmax) {
                    l[t*4+e] = p[j] * 0.125f;
                    mx = fmaxf(mx, l[t*4+e]);
                }
            }
        }
    }
    red[tid] = mx; __syncthreads();
    for (int s = 128; s > 0; s >>= 1) {
        if (tid < s) red[tid] = fmaxf(red[tid], red[tid + s]);
        __syncthreads();
    }
    mx = red[0]; __syncthreads();

    float sum = 0.f;
    #pragma unroll
    for (int t = 0; t < 4; t++) {
        const int q = tid + t * 256;
        #pragma unroll
        for (int e = 0; e < 4; e++) {
            const int j = q * 4 + e;
            if (j < jmax) {
                const float ex = __expf(l[t*4+e] - mx);
                l[t*4+e] = ex;
                sum += ex;
            }
        }
    }
    red[tid] = sum; __syncthreads();
    for (int s = 128; s > 0; s >>= 1) {
        if (tid < s) red[tid] += red[tid + s];
        __syncthreads();
    }
    const float inv = 1.f / red[0];

    #pragma unroll
    for (int t = 0; t < 4; t++) {
        const int q = tid + t * 256;
        if (q < full4) {
            float4 x;
            x.x = l[t*4+0] * inv; x.y = l[t*4+1] * inv;
            x.z = l[t*4+2] * inv; x.w = l[t*4+3] * inv;
            ((float4*)p)[q] = x;
        } else {
            #pragma unroll
            for (int e = 0; e < 4; e++) {
                const int j = q * 4 + e;
                if (j < jmax) p[j] = l[t*4+e] * inv;
            }
        }
    }
    for (int j = jmax + tid; j < K_LEN; j += 256) p[j] = 0.f;
}

// =============================================================================
// attn = P @ V per z, 3xBF16. BM=128 (i), BN=64 (d), banded k (keys).
// 8 warps 2x4, warp tile 64x16: MT=4, NT=2.
// =============================================================================
__global__ __launch_bounds__(256)
void gemm_attnv()
{
    const int i0 = blockIdx.x * 128;
    const int z = blockIdx.y;
    const int b = z >> 3, h = z & 7;
    const int kmax = i0 + 127 + M_MEM + 1;     // multiple of 16

    __shared__ uint32_t Ah[8][136], Al[8][136];
    __shared__ uint32_t Bh[8][72],  Bl[8][72];

    const int tid = threadIdx.x, lane = tid & 31, warp = tid >> 5;
    const int wm = (warp >> 2) * 64, wn = (warp & 3) * 16;
    const int pa = lane & 3, lm = lane >> 2;

    const int arow = tid >> 1;           // i within tile
    const int ak = (tid & 1) * 8;
    const int ap0 = ak >> 1;
    const float* aP = g_score + ((size_t)z * S_LEN + i0 + arow) * K_LEN + ak;

    const int bpr = tid >> 5;            // V k-pair row 0..7
    const int n2 = lane * 2;             // 0..62 (d)
    const float* vBase = g_qkv + ((size_t)(2 * bpr) * B_SZ + b) * QKV3
                       + 2 * HI + h * I_DIM + n2;
    const size_t vRow = (size_t)B_SZ * QKV3;

    float acc[8][4];
    #pragma unroll
    for (int t = 0; t < 8; t++) { acc[t][0]=acc[t][1]=acc[t][2]=acc[t][3]=0.f; }

    for (int k0 = 0; k0 < kmax; k0 += 16) {
        float4 av0 = *(const float4*)(aP + k0);
        float4 av1 = *(const float4*)(aP + k0 + 4);
        bf16_split2(av0.x, av0.y, Ah[ap0+0][arow], Al[ap0+0][arow]);
        bf16_split2(av0.z, av0.w, Ah[ap0+1][arow], Al[ap0+1][arow]);
        bf16_split2(av1.x, av1.y, Ah[ap0+2][arow], Al[ap0+2][arow]);
        bf16_split2(av1.z, av1.w, Ah[ap0+3][arow], Al[ap0+3][arow]);

        const float* vp = vBase + (size_t)k0 * vRow;
        float2 r0 = *(const float2*)vp;
        float2 r1 = *(const float2*)(vp + vRow);
        uint32_t h0,l0,h1,l1;
        bf16_split2(r0.x, r1.x, h0, l0);
        bf16_split2(r0.y, r1.y, h1, l1);
        *(uint2*)&Bh[bpr][n2] = make_uint2(h0, h1);
        *(uint2*)&Bl[bpr][n2] = make_uint2(l0, l1);
        __syncthreads();

        uint32_t bhf[2][2], blf[2][2];
        #pragma unroll
        for (int nt = 0; nt < 2; nt++) {
            const int n0 = wn + nt * 8 + lm;
            bhf[nt][0] = Bh[pa][n0];   bhf[nt][1] = Bh[pa+4][n0];
            blf[nt][0] = Bl[pa][n0];   blf[nt][1] = Bl[pa+4][n0];
        }
        #pragma unroll
        for (int mt = 0; mt < 4; mt++) {
            const int m0 = wm + mt * 16 + lm;
            uint32_t ah[4], al[4];
            ah[0] = Ah[pa][m0];    ah[1] = Ah[pa][m0+8];
            ah[2] = Ah[pa+4][m0];  ah[3] = Ah[pa+4][m0+8];
            al[0] = Al[pa][m0];    al[1] = Al[pa][m0+8];
            al[2] = Al[pa+4][m0];  al[3] = Al[pa+4][m0+8];
            #pragma unroll
            for (int nt = 0; nt < 2; nt++) {
                mma_bf16(acc[mt*2+nt], al, bhf[nt]);
                mma_bf16(acc[mt*2+nt], ah, blf[nt]);
                mma_bf16(acc[mt*2+nt], ah, bhf[nt]);
            }
        }
        __syncthreads();
    }

    #pragma unroll
    for (int mt = 0; mt < 4; mt++) {
        #pragma unroll
        for (int nt = 0; nt < 2; nt++) {
            const int i = i0 + wm + mt*16 + lm;
            const int d = wn + nt*8 + pa * 2;
            float* cp = g_attn + ((size_t)i * B_SZ + b) * E_DIM + h * I_DIM + d;
            cp[0] = acc[mt*2+nt][0]; cp[1] = acc[mt*2+nt][1];
            float* cp2 = g_attn + ((size_t)(i+8) * B_SZ + b) * E_DIM + h * I_DIM + d;
            cp2[0] = acc[mt*2+nt][2]; cp2[1] = acc[mt*2+nt][3];
        }
    }
}

// ---------------- residual (+optional extra bias) + LayerNorm ----------------
__global__ __launch_bounds__(256)
void ln_kernel(const float* __restrict__ x1, const float* __restrict__ x2,
               const float* __restrict__ extra_bias,
               const float* __restrict__ gamma, const float* __restrict__ beta,
               float* __restrict__ out)
{
    const int row = blockIdx.x;
    const int tid = threadIdx.x;
    const float* p1 = x1 + (size_t)row * E_DIM;
    const float* p2 = x2 + (size_t)row * E_DIM;
    float v0 = p1[tid] + p2[tid];
    float v1 = p1[tid + 256] + p2[tid + 256];
    if (extra_bias) { v0 += extra_bias[tid]; v1 += extra_bias[tid + 256]; }

    __shared__ float red[256];
    red[tid] = v0 + v1; __syncthreads();
    for (int s = 128; s > 0; s >>= 1) {
        if (tid < s) red[tid] += red[tid + s];
        __syncthreads();
    }
    const float mean = red[0] * (1.f / E_DIM);
    __syncthreads();
    const float d0 = v0 - mean, d1 = v1 - mean;
    red[tid] = d0 * d0 + d1 * d1; __syncthreads();
    for (int s = 128; s > 0; s >>= 1) {
        if (tid < s) red[tid] += red[tid + s];
        __syncthreads();
    }
    const float rstd = rsqrtf(red[0] * (1.f / E_DIM) + 1e-5f);
    out[(size_t)row * E_DIM + tid]       = d0 * rstd * gamma[tid]       + beta[tid];
    out[(size_t)row * E_DIM + tid + 256] = d1 * rstd * gamma[tid + 256] + beta[tid + 256];
}

// ---------------- launch ------------------------------------------------------
extern "C" void kernel_launch(void* const* d_in, const int* in_sizes, int n_in,
                              void* d_out, int out_size)
{
    const float* inputDec = (const float*)d_in[0];
    const float* posEmb   = (const float*)d_in[1];
    const float* u        = (const float*)d_in[2];
    const float* v        = (const float*)d_in[3];
    const float* memories = (const float*)d_in[4];
    const float* Wqkv     = (const float*)d_in[5];
    const float* Wr       = (const float*)d_in[6];
    const float* Wo       = (const float*)d_in[7];
    const float* ln1_g    = (const float*)d_in[8];
    const float* ln1_b    = (const float*)d_in[9];
    const float* W1       = (const float*)d_in[10];
    const float* b1       = (const float*)d_in[11];
    const float* W2       = (const float*)d_in[12];
    const float* b2       = (const float*)d_in[13];
    const float* ln2_g    = (const float*)d_in[14];
    const float* ln2_b    = (const float*)d_in[15];
    float* out = (float*)d_out;

    float *p_qkv, *p_r, *p_attn, *p_y, *p_ao, *p_h, *p_z;
    cudaGetSymbolAddress((void**)&p_qkv, g_qkv);
    cudaGetSymbolAddress((void**)&p_r, g_r);
    cudaGetSymbolAddress((void**)&p_attn, g_attn);
    cudaGetSymbolAddress((void**)&p_y, g_y);
    cudaGetSymbolAddress((void**)&p_ao, g_ao);
    cudaGetSymbolAddress((void**)&p_h, g_hidden);
    cudaGetSymbolAddress((void**)&p_z, g_z);

    // 1) qkv = concat(memories, inputDec) @ Wqkv     (8192 x 1536 x 512)
    gemm_dense<0,0><<<dim3(QKV3 / 128, (K_LEN * B_SZ) / 128), 256>>>(
        memories, inputDec, M_MEM * B_SZ, Wqkv, nullptr, p_qkv, QKV3, E_DIM);

    // 2) r = posEmbeddings @ Wr                      (4096 x 512 x 512)
    gemm_dense<0,0><<<dim3(HI / 128, K_LEN / 128), 256>>>(
        posEmb, posEmb, K_LEN, Wr, nullptr, p_r, HI, E_DIM);

    // 3) AC score GEMM (stores), then BD GEMM (rel-shift add in epilogue)
    gemm_score<0><<<dim3(K_LEN / 128, S_LEN / 128, B_SZ * H_HEADS), 256>>>(u);
    gemm_score<1><<<dim3(K_LEN / 128, S_LEN / 128, B_SZ * H_HEADS), 256>>>(v);

    // 4) softmax
    softmax_kernel<<<B_SZ * H_HEADS * S_LEN, 256>>>();

    // 5) attn = P @ V
    gemm_attnv<<<dim3(S_LEN / 128, B_SZ * H_HEADS), 256>>>();

    // 6) y = attn @ Wo                               (4096 x 512 x 512)
    gemm_dense<0,0><<<dim3(E_DIM / 128, (S_LEN * B_SZ) / 128), 256>>>(
        p_attn, p_attn, S_LEN * B_SZ, Wo, nullptr, p_y, E_DIM, HI);

    // 7) attn_out = LN(inputDec + y)
    ln_kernel<<<S_LEN * B_SZ, 256>>>(inputDec, p_y, nullptr, ln1_g, ln1_b, p_ao);

    // 8) hidden = relu(attn_out @ W1 + b1)           (4096 x 2048 x 512)
    gemm_dense<1,1><<<dim3(FF_DIM / 128, (S_LEN * B_SZ) / 128), 256>>>(
        p_ao, p_ao, S_LEN * B_SZ, W1, b1, p_h, FF_DIM, E_DIM);

    // 9) z = hidden @ W2                             (4096 x 512 x 2048)
    gemm_dense<0,0><<<dim3(E_DIM / 128, (S_LEN * B_SZ) / 128), 256>>>(
        p_h, p_h, S_LEN * B_SZ, W2, nullptr, p_z, E_DIM, FF_DIM);

    // 10) out = LN(attn_out + z + b2)
    ln_kernel<<<S_LEN * B_SZ, 256>>>(p_ao, p_z, b2, ln2_g, ln2_b, out);
}

// round 7
// speedup vs baseline: 2.2243x; 1.0148x over previous
#include <cuda_runtime.h>
#include <cuda_bf16.h>
#include <cstdint>
#include <cstddef>

#define S_LEN   2048
#define B_SZ    2
#define E_DIM   512
#define H_HEADS 8
#define I_DIM   64
#define M_MEM   2048
#define FF_DIM  2048
#define K_LEN   (M_MEM + S_LEN)      // 4096
#define HI      (H_HEADS * I_DIM)    // 512
#define QKV3    (3 * HI)             // 1536

// ---------------- scratch (device globals; no allocations allowed) ----------
__device__ float g_qkv   [(size_t)K_LEN * B_SZ * QKV3];            // 50 MB
__device__ float g_r     [(size_t)K_LEN * HI];                     //  8 MB
__device__ float g_score [(size_t)B_SZ * H_HEADS * S_LEN * K_LEN]; // 536 MB
__device__ float g_attn  [(size_t)S_LEN * B_SZ * E_DIM];
__device__ float g_y     [(size_t)S_LEN * B_SZ * E_DIM];
__device__ float g_ao    [(size_t)S_LEN * B_SZ * E_DIM];
__device__ float g_hidden[(size_t)S_LEN * B_SZ * FF_DIM];
__device__ float g_z     [(size_t)S_LEN * B_SZ * E_DIM];

// ---------------- bf16 split helpers -----------------------------------------
__device__ __forceinline__ void bf16_split2(float x0, float x1,
                                            uint32_t& hi, uint32_t& lo) {
    __nv_bfloat162 h = __floats2bfloat162_rn(x0, x1);
    float r0 = x0 - __low2float(h);
    float r1 = x1 - __high2float(h);
    __nv_bfloat162 l = __floats2bfloat162_rn(r0, r1);
    hi = *reinterpret_cast<uint32_t*>(&h);
    lo = *reinterpret_cast<uint32_t*>(&l);
}

__device__ __forceinline__ void mma_bf16(float c[4], const uint32_t a[4],
                                         const uint32_t b[2]) {
    asm volatile(
        "mma.sync.aligned.m16n8k16.row.col.f32.bf16.bf16.f32 "
        "{%0,%1,%2,%3},{%4,%5,%6,%7},{%8,%9},{%0,%1,%2,%3};\n"
        : "+f"(c[0]), "+f"(c[1]), "+f"(c[2]), "+f"(c[3])
        : "r"(a[0]), "r"(a[1]), "r"(a[2]), "r"(a[3]), "r"(b[0]), "r"(b[1]));
}

// smem pair arrays use stride 136 (or 72): stride % 32 == 8, so fragment
// access bank = (8*pair + item) % 32 is conflict-free for pair = base + (lane&3)
// with base % 4 == 0 and item = ... + (lane>>2).

// =============================================================================
// Dense GEMM: C(M,N) = gather(A)(M,Kd) @ B(Kd,N), 3xBF16 (hi/lo split).
// Block 128x128, K-chunk 32 (2 x k16 mma per sync pair), 8 warps (2x4),
// warp tile 64x32 (MT=4, NT=4).
// =============================================================================
template<int BIAS, int RELU>
__global__ __launch_bounds__(256, 2)
void gemm_dense(const float* __restrict__ A0, const float* __restrict__ A1,
                int splitRow, const float* __restrict__ Bm,
                const float* __restrict__ bias, float* __restrict__ C,
                int N, int Kd)
{
    __shared__ uint32_t Ah[16][136], Al[16][136];
    __shared__ uint32_t Bh[16][136], Bl[16][136];

    const int tid = threadIdx.x, lane = tid & 31, warp = tid >> 5;
    const int bm = blockIdx.y * 128, bn = blockIdx.x * 128;
    const int wm = (warp >> 2) * 64, wn = (warp & 3) * 32;
    const int pa = lane & 3, lm = lane >> 2;

    const int arow = tid >> 1;           // 0..127
    const int ahalf = tid & 1;           // k half of chunk
    const int apb = ahalf * 8;           // pair base 0 or 8
    const int grow = bm + arow;
    const float* aP = (grow < splitRow)
        ? (A0 + (size_t)grow * Kd) : (A1 + (size_t)(grow - splitRow) * Kd);

    const int pr = tid >> 4;             // B pair-row 0..15
    const int c8 = (tid & 15) * 8;       // col group of 8

    float acc[16][4];
    #pragma unroll
    for (int t = 0; t < 16; t++) { acc[t][0]=acc[t][1]=acc[t][2]=acc[t][3]=0.f; }

    for (int k0 = 0; k0 < Kd; k0 += 32) {
        // ---- A: 4 float4 (16 k) batched
        float4 a4[4];
        #pragma unroll
        for (int i = 0; i < 4; i++)
            a4[i] = *(const float4*)(aP + k0 + ahalf * 16 + 4 * i);
        #pragma unroll
        for (int i = 0; i < 4; i++) {
            uint32_t h0, l0, h1, l1;
            bf16_split2(a4[i].x, a4[i].y, h0, l0);
            bf16_split2(a4[i].z, a4[i].w, h1, l1);
            Ah[apb + 2*i][arow] = h0;  Al[apb + 2*i][arow] = l0;
            Ah[apb + 2*i + 1][arow] = h1;  Al[apb + 2*i + 1][arow] = l1;
        }
        // ---- B: rows k0+2pr, k0+2pr+1, cols bn+c8..+7 (4 float4 batched)
        const float* bRow0 = Bm + (size_t)(k0 + 2 * pr) * N + bn + c8;
        float4 b0a = ((const float4*)bRow0)[0];
        float4 b0b = ((const float4*)bRow0)[1];
        float4 b1a = ((const float4*)(bRow0 + N))[0];
        float4 b1b = ((const float4*)(bRow0 + N))[1];
        {
            uint32_t hh[8], ll[8];
            bf16_split2(b0a.x, b1a.x, hh[0], ll[0]);
            bf16_split2(b0a.y, b1a.y, hh[1], ll[1]);
            bf16_split2(b0a.z, b1a.z, hh[2], ll[2]);
            bf16_split2(b0a.w, b1a.w, hh[3], ll[3]);
            bf16_split2(b0b.x, b1b.x, hh[4], ll[4]);
            bf16_split2(b0b.y, b1b.y, hh[5], ll[5]);
            bf16_split2(b0b.z, b1b.z, hh[6], ll[6]);
            bf16_split2(b0b.w, b1b.w, hh[7], ll[7]);
            *(uint4*)&Bh[pr][c8]     = make_uint4(hh[0], hh[1], hh[2], hh[3]);
            *(uint4*)&Bh[pr][c8 + 4] = make_uint4(hh[4], hh[5], hh[6], hh[7]);
            *(uint4*)&Bl[pr][c8]     = make_uint4(ll[0], ll[1], ll[2], ll[3]);
            *(uint4*)&Bl[pr][c8 + 4] = make_uint4(ll[4], ll[5], ll[6], ll[7]);
        }
        __syncthreads();

        #pragma unroll
        for (int g = 0; g < 2; g++) {
            const int p0 = g * 8 + pa;
            uint32_t bhf[4][2], blf[4][2];
            #pragma unroll
            for (int nt = 0; nt < 4; nt++) {
                const int n0 = wn + nt * 8 + lm;
                bhf[nt][0] = Bh[p0][n0];     bhf[nt][1] = Bh[p0+4][n0];
                blf[nt][0] = Bl[p0][n0];     blf[nt][1] = Bl[p0+4][n0];
            }
            #pragma unroll
            for (int mt = 0; mt < 4; mt++) {
                const int m0 = wm + mt * 16 + lm;
                uint32_t ah[4], al[4];
                ah[0] = Ah[p0][m0];    ah[1] = Ah[p0][m0+8];
                ah[2] = Ah[p0+4][m0];  ah[3] = Ah[p0+4][m0+8];
                al[0] = Al[p0][m0];    al[1] = Al[p0][m0+8];
                al[2] = Al[p0+4][m0];  al[3] = Al[p0+4][m0+8];
                #pragma unroll
                for (int nt = 0; nt < 4; nt++) {
                    mma_bf16(acc[mt*4+nt], al, bhf[nt]);
                    mma_bf16(acc[mt*4+nt], ah, blf[nt]);
                    mma_bf16(acc[mt*4+nt], ah, bhf[nt]);
                }
            }
        }
        __syncthreads();
    }

    #pragma unroll
    for (int mt = 0; mt < 4; mt++) {
        #pragma unroll
        for (int nt = 0; nt < 4; nt++) {
            const int row = bm + wm + mt*16 + lm;
            const int col = bn + wn + nt*8 + pa * 2;
            const float* ap = acc[mt*4+nt];
            float v0 = ap[0], v1 = ap[1], v2 = ap[2], v3 = ap[3];
            if (BIAS) {
                const float bb0 = bias[col], bb1 = bias[col+1];
                v0 += bb0; v1 += bb1; v2 += bb0; v3 += bb1;
            }
            if (RELU) {
                v0 = fmaxf(v0, 0.f); v1 = fmaxf(v1, 0.f);
                v2 = fmaxf(v2, 0.f); v3 = fmaxf(v3, 0.f);
            }
            float* cp = C + (size_t)row * N + col;
            cp[0] = v0; cp[1] = v1;
            cp[(size_t)8 * N] = v2; cp[(size_t)8 * N + 1] = v3;
        }
    }
}

// =============================================================================
// Score GEMMs, 3xBF16, single-shot K=64 staging (dynamic smem 69632 B).
//   IS_BD=0: score[z][i][j] = sum_d (q[i,d]+u[d]) * k[j,d]      (plain store)
//   IS_BD=1: Bt[i][jj] = sum_d (q[i,d]+v[d]) * r[jj,d]; epilogue applies the
//            rel-shift inline: score[z][i][jj-(S-1-i)] += Bt  (when idx >= 0).
// All 16 global float4 loads per thread are issued in one batch, ONE sync,
// then 12 k16-mma groups run uninterrupted.
// =============================================================================
#define SCORE_SMEM_BYTES 69632
template<int IS_BD>
__global__ __launch_bounds__(256, 2)
void gemm_score(const float* __restrict__ uv)
{
    const int j0 = blockIdx.x * 128;
    const int i0 = blockIdx.y * 128;
    if (!IS_BD && j0 > i0 + 127 + M_MEM) return;       // fully masked
    if (IS_BD && (i0 + j0 < S_LEN - 255)) return;      // shift target < 0 always
    const int z = blockIdx.z;
    const int b = z >> 3, h = z & 7;

    extern __shared__ uint32_t dsm[];
    uint32_t* AH = dsm;                 // [32][136]
    uint32_t* AL = dsm + 4352;
    uint32_t* BH = dsm + 8704;
    uint32_t* BL = dsm + 13056;

    const int tid = threadIdx.x, lane = tid & 31, warp = tid >> 5;
    const int wm = (warp >> 2) * 64, wn = (warp & 3) * 32;
    const int pa = lane & 3, lm = lane >> 2;

    const int row = tid >> 1;            // 0..127 (both A and B tiles)
    const int half = tid & 1;            // k half (32 each)
    const int pb = half * 16;            // pair base

    const float* aP = g_qkv
        + ((size_t)(M_MEM + i0 + row) * B_SZ + b) * QKV3 + h * I_DIM + half * 32;
    const float* uvP = uv + h * I_DIM + half * 32;
    const float* bP = IS_BD
        ? (g_r + (size_t)(j0 + row) * HI + h * I_DIM + half * 32)
        : (g_qkv + ((size_t)(j0 + row) * B_SZ + b) * QKV3 + HI + h * I_DIM + half * 32);

    // ---- batched loads (A + uv), convert, store
    {
        float4 a4[8], u4[8];
        #pragma unroll
        for (int p = 0; p < 8; p++) a4[p] = ((const float4*)aP)[p];
        #pragma unroll
        for (int p = 0; p < 8; p++) u4[p] = ((const float4*)uvP)[p];
        #pragma unroll
        for (int p = 0; p < 8; p++) {
            uint32_t h0, l0, h1, l1;
            bf16_split2(a4[p].x + u4[p].x, a4[p].y + u4[p].y, h0, l0);
            bf16_split2(a4[p].z + u4[p].z, a4[p].w + u4[p].w, h1, l1);
            AH[(pb + 2*p) * 136 + row] = h0;  AL[(pb + 2*p) * 136 + row] = l0;
            AH[(pb + 2*p + 1) * 136 + row] = h1;  AL[(pb + 2*p + 1) * 136 + row] = l1;
        }
    }
    {
        float4 b4[8];
        #pragma unroll
        for (int p = 0; p < 8; p++) b4[p] = ((const float4*)bP)[p];
        #pragma unroll
        for (int p = 0; p < 8; p++) {
            uint32_t h0, l0, h1, l1;
            bf16_split2(b4[p].x, b4[p].y, h0, l0);
            bf16_split2(b4[p].z, b4[p].w, h1, l1);
            BH[(pb + 2*p) * 136 + row] = h0;  BL[(pb + 2*p) * 136 + row] = l0;
            BH[(pb + 2*p + 1) * 136 + row] = h1;  BL[(pb + 2*p + 1) * 136 + row] = l1;
        }
    }
    __syncthreads();

    float acc[16][4];
    #pragma unroll
    for (int t = 0; t < 16; t++) { acc[t][0]=acc[t][1]=acc[t][2]=acc[t][3]=0.f; }

    #pragma unroll
    for (int g = 0; g < 4; g++) {
        const int p0 = g * 8 + pa;
        uint32_t bhf[4][2], blf[4][2];
        #pragma unroll
        for (int nt = 0; nt < 4; nt++) {
            const int n0 = wn + nt * 8 + lm;
            bhf[nt][0] = BH[p0 * 136 + n0];      bhf[nt][1] = BH[(p0+4) * 136 + n0];
            blf[nt][0] = BL[p0 * 136 + n0];      blf[nt][1] = BL[(p0+4) * 136 + n0];
        }
        #pragma unroll
        for (int mt = 0; mt < 4; mt++) {
            const int m0 = wm + mt * 16 + lm;
            uint32_t ah[4], al[4];
            ah[0] = AH[p0 * 136 + m0];     ah[1] = AH[p0 * 136 + m0 + 8];
            ah[2] = AH[(p0+4) * 136 + m0]; ah[3] = AH[(p0+4) * 136 + m0 + 8];
            al[0] = AL[p0 * 136 + m0];     al[1] = AL[p0 * 136 + m0 + 8];
            al[2] = AL[(p0+4) * 136 + m0]; al[3] = AL[(p0+4) * 136 + m0 + 8];
            #pragma unroll
            for (int nt = 0; nt < 4; nt++) {
                mma_bf16(acc[mt*4+nt], al, bhf[nt]);
                mma_bf16(acc[mt*4+nt], ah, blf[nt]);
                mma_bf16(acc[mt*4+nt], ah, bhf[nt]);
            }
        }
    }

    float* Cbase = g_score + (size_t)z * S_LEN * K_LEN;
    #pragma unroll
    for (int mt = 0; mt < 4; mt++) {
        #pragma unroll
        for (int nt = 0; nt < 4; nt++) {
            const int r0 = i0 + wm + mt*16 + lm;
            const int c0 = j0 + wn + nt*8 + pa * 2;
            if (!IS_BD) {
                float* cp = Cbase + (size_t)r0 * K_LEN + c0;
                cp[0] = acc[mt*4+nt][0]; cp[1] = acc[mt*4+nt][1];
                cp[(size_t)8 * K_LEN] = acc[mt*4+nt][2];
                cp[(size_t)8 * K_LEN + 1] = acc[mt*4+nt][3];
            } else {
                // rel-shift: score[i][jj - (S-1-i)] += Bt[i][jj]
                const int sh0 = c0 - (S_LEN - 1 - r0);         // j for row r0
                const int sh1 = c0 - (S_LEN - 1 - (r0 + 8));   // j for row r0+8
                float* cp0 = Cbase + (size_t)r0 * K_LEN + sh0;
                float* cp1 = Cbase + (size_t)(r0 + 8) * K_LEN + sh1;
                if (sh0 >= 0)     cp0[0] += acc[mt*4+nt][0];
                if (sh0 + 1 >= 0) cp0[1] += acc[mt*4+nt][1];
                if (sh1 >= 0)     cp1[0] += acc[mt*4+nt][2];
                if (sh1 + 1 >= 0) cp1[1] += acc[mt*4+nt][3];
            }
        }
    }
}

// =============================================================================
// Softmax: logits = score[i,j] / 8 over j in [0, i+m]; zero the masked tail.
// float4-vectorized, register-stashed: 1 read + 1 write of the row.
// =============================================================================
__global__ __launch_bounds__(256)
void softmax_kernel()
{
    const int rowid = blockIdx.x;              // z*S + i
    const int i = rowid & (S_LEN - 1);
    float* p = g_score + (size_t)rowid * K_LEN;
    const int jmax = i + M_MEM + 1;
    const int full4 = jmax >> 2;               // complete float4s
    const int tid = threadIdx.x;
    __shared__ float red[256];

    float l[16];
    float mx = -1e30f;
    #pragma unroll
    for (int t = 0; t < 4; t++) {
        const int q = tid + t * 256;           // float4 index, 0..1023
        if (q < full4) {
            float4 x = ((const float4*)p)[q];
            l[t*4+0] = x.x * 0.125f; l[t*4+1] = x.y * 0.125f;
            l[t*4+2] = x.z * 0.125f; l[t*4+3] = x.w * 0.125f;
            mx = fmaxf(mx, fmaxf(fmaxf(l[t*4+0], l[t*4+1]),
                                 fmaxf(l[t*4+2], l[t*4+3])));
        } else {
            #pragma unroll
            for (int e = 0; e < 4; e++) {
                const int j = q * 4 + e;
                if (j < jmax) {
                    l[t*4+e] = p[j] * 0.125f;
                    mx = fmaxf(mx, l[t*4+e]);
                }
            }
        }
    }
    red[tid] = mx; __syncthreads();
    for (int s = 128; s > 0; s >>= 1) {
        if (tid < s) red[tid] = fmaxf(red[tid], red[tid + s]);
        __syncthreads();
    }
    mx = red[0]; __syncthreads();

    float sum = 0.f;
    #pragma unroll
    for (int t = 0; t < 4; t++) {
        const int q = tid + t * 256;
        #pragma unroll
        for (int e = 0; e < 4; e++) {
            const int j = q * 4 + e;
            if (j < jmax) {
                const float ex = __expf(l[t*4+e] - mx);
                l[t*4+e] = ex;
                sum += ex;
            }
        }
    }
    red[tid] = sum; __syncthreads();
    for (int s = 128; s > 0; s >>= 1) {
        if (tid < s) red[tid] += red[tid + s];
        __syncthreads();
    }
    const float inv = 1.f / red[0];

    #pragma unroll
    for (int t = 0; t < 4; t++) {
        const int q = tid + t * 256;
        if (q < full4) {
            float4 x;
            x.x = l[t*4+0] * inv; x.y = l[t*4+1] * inv;
            x.z = l[t*4+2] * inv; x.w = l[t*4+3] * inv;
            ((float4*)p)[q] = x;
        } else {
            #pragma unroll
            for (int e = 0; e < 4; e++) {
                const int j = q * 4 + e;
                if (j < jmax) p[j] = l[t*4+e] * inv;
            }
        }
    }
    for (int j = jmax + tid; j < K_LEN; j += 256) p[j] = 0.f;
}

// =============================================================================
// attn = P @ V per z, 3xBF16, K-chunk 32. BM=128 (i), BN=64 (d), banded k.
// 8 warps 2x4, warp tile 64x16: MT=4, NT=2.
// =============================================================================
__global__ __launch_bounds__(256, 2)
void gemm_attnv()
{
    const int i0 = blockIdx.x * 128;
    const int z = blockIdx.y;
    const int b = z >> 3, h = z & 7;
    const int kmax = i0 + 127 + M_MEM + 1;     // multiple of 32

    __shared__ uint32_t Ah[16][136], Al[16][136];
    __shared__ uint32_t Bh[16][72],  Bl[16][72];

    const int tid = threadIdx.x, lane = tid & 31, warp = tid >> 5;
    const int wm = (warp >> 2) * 64, wn = (warp & 3) * 16;
    const int pa = lane & 3, lm = lane >> 2;

    const int arow = tid >> 1;           // i within tile
    const int ahalf = tid & 1;
    const int apb = ahalf * 8;
    const float* aP = g_score + ((size_t)z * S_LEN + i0 + arow) * K_LEN;

    const int pr = tid >> 4;             // V pair-row 0..15
    const int c4 = (tid & 15) * 4;       // d group of 4
    const float* vBase = g_qkv + ((size_t)(2 * pr) * B_SZ + b) * QKV3
                       + 2 * HI + h * I_DIM + c4;
    const size_t vRow = (size_t)B_SZ * QKV3;

    float acc[8][4];
    #pragma unroll
    for (int t = 0; t < 8; t++) { acc[t][0]=acc[t][1]=acc[t][2]=acc[t][3]=0.f; }

    for (int k0 = 0; k0 < kmax; k0 += 32) {
        // ---- P: 4 float4 batched (16 k)
        float4 a4[4];
        #pragma unroll
        for (int i = 0; i < 4; i++)
            a4[i] = *(const float4*)(aP + k0 + ahalf * 16 + 4 * i);
        #pragma unroll
        for (int i = 0; i < 4; i++) {
            uint32_t h0, l0, h1, l1;
            bf16_split2(a4[i].x, a4[i].y, h0, l0);
            bf16_split2(a4[i].z, a4[i].w, h1, l1);
            Ah[apb + 2*i][arow] = h0;  Al[apb + 2*i][arow] = l0;
            Ah[apb + 2*i + 1][arow] = h1;  Al[apb + 2*i + 1][arow] = l1;
        }
        // ---- V: rows k0+2pr, k0+2pr+1, cols c4..c4+3
        const float* vp = vBase + (size_t)k0 * vRow;
        float4 v0 = *(const float4*)vp;
        float4 v1 = *(const float4*)(vp + vRow);
        {
            uint32_t hh[4], ll[4];
            bf16_split2(v0.x, v1.x, hh[0], ll[0]);
            bf16_split2(v0.y, v1.y, hh[1], ll[1]);
            bf16_split2(v0.z, v1.z, hh[2], ll[2]);
            bf16_split2(v0.w, v1.w, hh[3], ll[3]);
            *(uint4*)&Bh[pr][c4] = make_uint4(hh[0], hh[1], hh[2], hh[3]);
            *(uint4*)&Bl[pr][c4] = make_uint4(ll[0], ll[1], ll[2], ll[3]);
        }
        __syncthreads();

        #pragma unroll
        for (int g = 0; g < 2; g++) {
            const int p0 = g * 8 + pa;
            uint32_t bhf[2][2], blf[2][2];
            #pragma unroll
            for (int nt = 0; nt < 2; nt++) {
                const int n0 = wn + nt * 8 + lm;
                bhf[nt][0] = Bh[p0][n0];   bhf[nt][1] = Bh[p0+4][n0];
                blf[nt][0] = Bl[p0][n0];   blf[nt][1] = Bl[p0+4][n0];
            }
            #pragma unroll
            for (int mt = 0; mt < 4; mt++) {
                const int m0 = wm + mt * 16 + lm;
                uint32_t ah[4], al[4];
                ah[0] = Ah[p0][m0];    ah[1] = Ah[p0][m0+8];
                ah[2] = Ah[p0+4][m0];  ah[3] = Ah[p0+4][m0+8];
                al[0] = Al[p0][m0];    al[1] = Al[p0][m0+8];
                al[2] = Al[p0+4][m0];  al[3] = Al[p0+4][m0+8];
                #pragma unroll
                for (int nt = 0; nt < 2; nt++) {
                    mma_bf16(acc[mt*2+nt], al, bhf[nt]);
                    mma_bf16(acc[mt*2+nt], ah, blf[nt]);
                    mma_bf16(acc[mt*2+nt], ah, bhf[nt]);
                }
            }
        }
        __syncthreads();
    }

    #pragma unroll
    for (int mt = 0; mt < 4; mt++) {
        #pragma unroll
        for (int nt = 0; nt < 2; nt++) {
            const int i = i0 + wm + mt*16 + lm;
            const int d = wn + nt*8 + pa * 2;
            float* cp = g_attn + ((size_t)i * B_SZ + b) * E_DIM + h * I_DIM + d;
            cp[0] = acc[mt*2+nt][0]; cp[1] = acc[mt*2+nt][1];
            float* cp2 = g_attn + ((size_t)(i+8) * B_SZ + b) * E_DIM + h * I_DIM + d;
            cp2[0] = acc[mt*2+nt][2]; cp2[1] = acc[mt*2+nt][3];
        }
    }
}

// ---------------- residual (+optional extra bias) + LayerNorm ----------------
__global__ __launch_bounds__(256)
void ln_kernel(const float* __restrict__ x1, const float* __restrict__ x2,
               const float* __restrict__ extra_bias,
               const float* __restrict__ gamma, const float* __restrict__ beta,
               float* __restrict__ out)
{
    const int row = blockIdx.x;
    const int tid = threadIdx.x;
    const float* p1 = x1 + (size_t)row * E_DIM;
    const float* p2 = x2 + (size_t)row * E_DIM;
    float v0 = p1[tid] + p2[tid];
    float v1 = p1[tid + 256] + p2[tid + 256];
    if (extra_bias) { v0 += extra_bias[tid]; v1 += extra_bias[tid + 256]; }

    __shared__ float red[256];
    red[tid] = v0 + v1; __syncthreads();
    for (int s = 128; s > 0; s >>= 1) {
        if (tid < s) red[tid] += red[tid + s];
        __syncthreads();
    }
    const float mean = red[0] * (1.f / E_DIM);
    __syncthreads();
    const float d0 = v0 - mean, d1 = v1 - mean;
    red[tid] = d0 * d0 + d1 * d1; __syncthreads();
    for (int s = 128; s > 0; s >>= 1) {
        if (tid < s) red[tid] += red[tid + s];
        __syncthreads();
    }
    const float rstd = rsqrtf(red[0] * (1.f / E_DIM) + 1e-5f);
    out[(size_t)row * E_DIM + tid]       = d0 * rstd * gamma[tid]       + beta[tid];
    out[(size_t)row * E_DIM + tid + 256] = d1 * rstd * gamma[tid + 256] + beta[tid + 256];
}

// ---------------- launch ------------------------------------------------------
extern "C" void kernel_launch(void* const* d_in, const int* in_sizes, int n_in,
                              void* d_out, int out_size)
{
    const float* inputDec = (const float*)d_in[0];
    const float* posEmb   = (const float*)d_in[1];
    const float* u        = (const float*)d_in[2];
    const float* v        = (const float*)d_in[3];
    const float* memories = (const float*)d_in[4];
    const float* Wqkv     = (const float*)d_in[5];
    const float* Wr       = (const float*)d_in[6];
    const float* Wo       = (const float*)d_in[7];
    const float* ln1_g    = (const float*)d_in[8];
    const float* ln1_b    = (const float*)d_in[9];
    const float* W1       = (const float*)d_in[10];
    const float* b1       = (const float*)d_in[11];
    const float* W2       = (const float*)d_in[12];
    const float* b2       = (const float*)d_in[13];
    const float* ln2_g    = (const float*)d_in[14];
    const float* ln2_b    = (const float*)d_in[15];
    float* out = (float*)d_out;

    float *p_qkv, *p_r, *p_attn, *p_y, *p_ao, *p_h, *p_z;
    cudaGetSymbolAddress((void**)&p_qkv, g_qkv);
    cudaGetSymbolAddress((void**)&p_r, g_r);
    cudaGetSymbolAddress((void**)&p_attn, g_attn);
    cudaGetSymbolAddress((void**)&p_y, g_y);
    cudaGetSymbolAddress((void**)&p_ao, g_ao);
    cudaGetSymbolAddress((void**)&p_h, g_hidden);
    cudaGetSymbolAddress((void**)&p_z, g_z);

    // Opt-in to >48KB dynamic smem for score kernels (idempotent, capture-safe)
    cudaFuncSetAttribute(gemm_score<0>,
        cudaFuncAttributeMaxDynamicSharedMemorySize, SCORE_SMEM_BYTES);
    cudaFuncSetAttribute(gemm_score<1>,
        cudaFuncAttributeMaxDynamicSharedMemorySize, SCORE_SMEM_BYTES);

    // 1) qkv = concat(memories, inputDec) @ Wqkv     (8192 x 1536 x 512)
    gemm_dense<0,0><<<dim3(QKV3 / 128, (K_LEN * B_SZ) / 128), 256>>>(
        memories, inputDec, M_MEM * B_SZ, Wqkv, nullptr, p_qkv, QKV3, E_DIM);

    // 2) r = posEmbeddings @ Wr                      (4096 x 512 x 512)
    gemm_dense<0,0><<<dim3(HI / 128, K_LEN / 128), 256>>>(
        posEmb, posEmb, K_LEN, Wr, nullptr, p_r, HI, E_DIM);

    // 3) AC score GEMM (stores), then BD GEMM (rel-shift add in epilogue)
    gemm_score<0><<<dim3(K_LEN / 128, S_LEN / 128, B_SZ * H_HEADS), 256,
                    SCORE_SMEM_BYTES>>>(u);
    gemm_score<1><<<dim3(K_LEN / 128, S_LEN / 128, B_SZ * H_HEADS), 256,
                    SCORE_SMEM_BYTES>>>(v);

    // 4) softmax
    softmax_kernel<<<B_SZ * H_HEADS * S_LEN, 256>>>();

    // 5) attn = P @ V
    gemm_attnv<<<dim3(S_LEN / 128, B_SZ * H_HEADS), 256>>>();

    // 6) y = attn @ Wo                               (4096 x 512 x 512)
    gemm_dense<0,0><<<dim3(E_DIM / 128, (S_LEN * B_SZ) / 128), 256>>>(
        p_attn, p_attn, S_LEN * B_SZ, Wo, nullptr, p_y, E_DIM, HI);

    // 7) attn_out = LN(inputDec + y)
    ln_kernel<<<S_LEN * B_SZ, 256>>>(inputDec, p_y, nullptr, ln1_g, ln1_b, p_ao);

    // 8) hidden = relu(attn_out @ W1 + b1)           (4096 x 2048 x 512)
    gemm_dense<1,1><<<dim3(FF_DIM / 128, (S_LEN * B_SZ) / 128), 256>>>(
        p_ao, p_ao, S_LEN * B_SZ, W1, b1, p_h, FF_DIM, E_DIM);

    // 9) z = hidden @ W2                             (4096 x 512 x 2048)
    gemm_dense<0,0><<<dim3(E_DIM / 128, (S_LEN * B_SZ) / 128), 256>>>(
        p_h, p_h, S_LEN * B_SZ, W2, nullptr, p_z, E_DIM, FF_DIM);

    // 10) out = LN(attn_out + z + b2)
    ln_kernel<<<S_LEN * B_SZ, 256>>>(p_ao, p_z, b2, ln2_g, ln2_b, out);
}

// round 8
// speedup vs baseline: 2.8780x; 1.2939x over previous
#include <cuda_runtime.h>
#include <cuda_bf16.h>
#include <cstdint>
#include <cstddef>

#define S_LEN   2048
#define B_SZ    2
#define E_DIM   512
#define H_HEADS 8
#define I_DIM   64
#define M_MEM   2048
#define FF_DIM  2048
#define K_LEN   (M_MEM + S_LEN)      // 4096
#define HI      (H_HEADS * I_DIM)    // 512
#define QKV3    (3 * HI)             // 1536

// ---------------- scratch (device globals; no allocations allowed) ----------
__device__ float g_qkv   [(size_t)K_LEN * B_SZ * QKV3];            // 50 MB
__device__ float g_r     [(size_t)K_LEN * HI];                     //  8 MB
__device__ float g_score [(size_t)B_SZ * H_HEADS * S_LEN * K_LEN]; // 536 MB
__device__ float g_attn  [(size_t)S_LEN * B_SZ * E_DIM];
__device__ float g_y     [(size_t)S_LEN * B_SZ * E_DIM];
__device__ float g_ao    [(size_t)S_LEN * B_SZ * E_DIM];
__device__ float g_hidden[(size_t)S_LEN * B_SZ * FF_DIM];
__device__ float g_z     [(size_t)S_LEN * B_SZ * E_DIM];

// ---------------- bf16 split helpers -----------------------------------------
__device__ __forceinline__ void bf16_split2(float x0, float x1,
                                            uint32_t& hi, uint32_t& lo) {
    __nv_bfloat162 h = __floats2bfloat162_rn(x0, x1);
    float r0 = x0 - __low2float(h);
    float r1 = x1 - __high2float(h);
    __nv_bfloat162 l = __floats2bfloat162_rn(r0, r1);
    hi = *reinterpret_cast<uint32_t*>(&h);
    lo = *reinterpret_cast<uint32_t*>(&l);
}

__device__ __forceinline__ void mma_bf16(float c[4], const uint32_t a[4],
                                         const uint32_t b[2]) {
    asm volatile(
        "mma.sync.aligned.m16n8k16.row.col.f32.bf16.bf16.f32 "
        "{%0,%1,%2,%3},{%4,%5,%6,%7},{%8,%9},{%0,%1,%2,%3};\n"
        : "+f"(c[0]), "+f"(c[1]), "+f"(c[2]), "+f"(c[3])
        : "r"(a[0]), "r"(a[1]), "r"(a[2]), "r"(a[3]), "r"(b[0]), "r"(b[1]));
}

// smem pair arrays use stride 136 (or 72): stride % 32 == 8, so fragment
// access bank = (8*pair + item) % 32 is conflict-free for pair = base + (lane&3)
// with base % 4 == 0 and item = ... + (lane>>2).

// =============================================================================
// Dense GEMM: C(M,N) = gather(A)(M,Kd) @ B(Kd,N), 3xBF16 (hi/lo split).
// Block 128x128, K-chunk 32 (2 x k16 mma per sync pair), 8 warps (2x4),
// warp tile 64x32 (MT=4, NT=4).
// =============================================================================
template<int BIAS, int RELU>
__global__ __launch_bounds__(256, 2)
void gemm_dense(const float* __restrict__ A0, const float* __restrict__ A1,
                int splitRow, const float* __restrict__ Bm,
                const float* __restrict__ bias, float* __restrict__ C,
                int N, int Kd)
{
    __shared__ uint32_t Ah[16][136], Al[16][136];
    __shared__ uint32_t Bh[16][136], Bl[16][136];

    const int tid = threadIdx.x, lane = tid & 31, warp = tid >> 5;
    const int bm = blockIdx.y * 128, bn = blockIdx.x * 128;
    const int wm = (warp >> 2) * 64, wn = (warp & 3) * 32;
    const int pa = lane & 3, lm = lane >> 2;

    const int arow = tid >> 1;           // 0..127
    const int ahalf = tid & 1;           // k half of chunk
    const int apb = ahalf * 8;           // pair base 0 or 8
    const int grow = bm + arow;
    const float* aP = (grow < splitRow)
        ? (A0 + (size_t)grow * Kd) : (A1 + (size_t)(grow - splitRow) * Kd);

    const int pr = tid >> 4;             // B pair-row 0..15
    const int c8 = (tid & 15) * 8;       // col group of 8

    float acc[16][4];
    #pragma unroll
    for (int t = 0; t < 16; t++) { acc[t][0]=acc[t][1]=acc[t][2]=acc[t][3]=0.f; }

    for (int k0 = 0; k0 < Kd; k0 += 32) {
        // ---- A: 4 float4 (16 k) batched
        float4 a4[4];
        #pragma unroll
        for (int i = 0; i < 4; i++)
            a4[i] = *(const float4*)(aP + k0 + ahalf * 16 + 4 * i);
        #pragma unroll
        for (int i = 0; i < 4; i++) {
            uint32_t h0, l0, h1, l1;
            bf16_split2(a4[i].x, a4[i].y, h0, l0);
            bf16_split2(a4[i].z, a4[i].w, h1, l1);
            Ah[apb + 2*i][arow] = h0;  Al[apb + 2*i][arow] = l0;
            Ah[apb + 2*i + 1][arow] = h1;  Al[apb + 2*i + 1][arow] = l1;
        }
        // ---- B: rows k0+2pr, k0+2pr+1, cols bn+c8..+7 (4 float4 batched)
        const float* bRow0 = Bm + (size_t)(k0 + 2 * pr) * N + bn + c8;
        float4 b0a = ((const float4*)bRow0)[0];
        float4 b0b = ((const float4*)bRow0)[1];
        float4 b1a = ((const float4*)(bRow0 + N))[0];
        float4 b1b = ((const float4*)(bRow0 + N))[1];
        {
            uint32_t hh[8], ll[8];
            bf16_split2(b0a.x, b1a.x, hh[0], ll[0]);
            bf16_split2(b0a.y, b1a.y, hh[1], ll[1]);
            bf16_split2(b0a.z, b1a.z, hh[2], ll[2]);
            bf16_split2(b0a.w, b1a.w, hh[3], ll[3]);
            bf16_split2(b0b.x, b1b.x, hh[4], ll[4]);
            bf16_split2(b0b.y, b1b.y, hh[5], ll[5]);
            bf16_split2(b0b.z, b1b.z, hh[6], ll[6]);
            bf16_split2(b0b.w, b1b.w, hh[7], ll[7]);
            *(uint4*)&Bh[pr][c8]     = make_uint4(hh[0], hh[1], hh[2], hh[3]);
            *(uint4*)&Bh[pr][c8 + 4] = make_uint4(hh[4], hh[5], hh[6], hh[7]);
            *(uint4*)&Bl[pr][c8]     = make_uint4(ll[0], ll[1], ll[2], ll[3]);
            *(uint4*)&Bl[pr][c8 + 4] = make_uint4(ll[4], ll[5], ll[6], ll[7]);
        }
        __syncthreads();

        #pragma unroll
        for (int g = 0; g < 2; g++) {
            const int p0 = g * 8 + pa;
            uint32_t bhf[4][2], blf[4][2];
            #pragma unroll
            for (int nt = 0; nt < 4; nt++) {
                const int n0 = wn + nt * 8 + lm;
                bhf[nt][0] = Bh[p0][n0];     bhf[nt][1] = Bh[p0+4][n0];
                blf[nt][0] = Bl[p0][n0];     blf[nt][1] = Bl[p0+4][n0];
            }
            #pragma unroll
            for (int mt = 0; mt < 4; mt++) {
                const int m0 = wm + mt * 16 + lm;
                uint32_t ah[4], al[4];
                ah[0] = Ah[p0][m0];    ah[1] = Ah[p0][m0+8];
                ah[2] = Ah[p0+4][m0];  ah[3] = Ah[p0+4][m0+8];
                al[0] = Al[p0][m0];    al[1] = Al[p0][m0+8];
                al[2] = Al[p0+4][m0];  al[3] = Al[p0+4][m0+8];
                #pragma unroll
                for (int nt = 0; nt < 4; nt++) {
                    mma_bf16(acc[mt*4+nt], al, bhf[nt]);
                    mma_bf16(acc[mt*4+nt], ah, blf[nt]);
                    mma_bf16(acc[mt*4+nt], ah, bhf[nt]);
                }
            }
        }
        __syncthreads();
    }

    #pragma unroll
    for (int mt = 0; mt < 4; mt++) {
        #pragma unroll
        for (int nt = 0; nt < 4; nt++) {
            const int row = bm + wm + mt*16 + lm;
            const int col = bn + wn + nt*8 + pa * 2;
            const float* ap = acc[mt*4+nt];
            float v0 = ap[0], v1 = ap[1], v2 = ap[2], v3 = ap[3];
            if (BIAS) {
                const float bb0 = bias[col], bb1 = bias[col+1];
                v0 += bb0; v1 += bb1; v2 += bb0; v3 += bb1;
            }
            if (RELU) {
                v0 = fmaxf(v0, 0.f); v1 = fmaxf(v1, 0.f);
                v2 = fmaxf(v2, 0.f); v3 = fmaxf(v3, 0.f);
            }
            float* cp = C + (size_t)row * N + col;
            cp[0] = v0; cp[1] = v1;
            cp[(size_t)8 * N] = v2; cp[(size_t)8 * N + 1] = v3;
        }
    }
}

// =============================================================================
// Score GEMMs, 3xBF16, single-shot K=64 staging (dynamic smem 69632 B).
//   IS_BD=0: score[z][i][j] = sum_d (q[i,d]+u[d]) * k[j,d]      (plain store)
//   IS_BD=1: Bt[i][jj] = sum_d (q[i,d]+v[d]) * r[jj,d]; epilogue applies the
//            rel-shift inline: score[z][i][jj-(S-1-i)] += Bt  (when idx >= 0).
// Epilogue is staged through smem (reusing the dead operand region) so the
// global phase is warp-per-row COALESCED: float4 stores for AC, consecutive-
// lane scalar RMW for BD.
// =============================================================================
#define SCORE_SMEM_BYTES 69632
template<int IS_BD>
__global__ __launch_bounds__(256, 2)
void gemm_score(const float* __restrict__ uv)
{
    const int j0 = blockIdx.x * 128;
    const int i0 = blockIdx.y * 128;
    if (!IS_BD && j0 > i0 + 127 + M_MEM) return;       // fully masked
    if (IS_BD && (i0 + j0 < S_LEN - 255)) return;      // shift target < 0 always
    const int z = blockIdx.z;
    const int b = z >> 3, h = z & 7;

    extern __shared__ uint32_t dsm[];
    uint32_t* AH = dsm;                 // [32][136]
    uint32_t* AL = dsm + 4352;
    uint32_t* BH = dsm + 8704;
    uint32_t* BL = dsm + 13056;

    const int tid = threadIdx.x, lane = tid & 31, warp = tid >> 5;
    const int wm = (warp >> 2) * 64, wn = (warp & 3) * 32;
    const int pa = lane & 3, lm = lane >> 2;

    const int row = tid >> 1;            // 0..127 (both A and B tiles)
    const int half = tid & 1;            // k half (32 each)
    const int pb = half * 16;            // pair base

    const float* aP = g_qkv
        + ((size_t)(M_MEM + i0 + row) * B_SZ + b) * QKV3 + h * I_DIM + half * 32;
    const float* uvP = uv + h * I_DIM + half * 32;
    const float* bP = IS_BD
        ? (g_r + (size_t)(j0 + row) * HI + h * I_DIM + half * 32)
        : (g_qkv + ((size_t)(j0 + row) * B_SZ + b) * QKV3 + HI + h * I_DIM + half * 32);

    // ---- batched loads (A + uv), convert, store
    {
        float4 a4[8], u4[8];
        #pragma unroll
        for (int p = 0; p < 8; p++) a4[p] = ((const float4*)aP)[p];
        #pragma unroll
        for (int p = 0; p < 8; p++) u4[p] = ((const float4*)uvP)[p];
        #pragma unroll
        for (int p = 0; p < 8; p++) {
            uint32_t h0, l0, h1, l1;
            bf16_split2(a4[p].x + u4[p].x, a4[p].y + u4[p].y, h0, l0);
            bf16_split2(a4[p].z + u4[p].z, a4[p].w + u4[p].w, h1, l1);
            AH[(pb + 2*p) * 136 + row] = h0;  AL[(pb + 2*p) * 136 + row] = l0;
            AH[(pb + 2*p + 1) * 136 + row] = h1;  AL[(pb + 2*p + 1) * 136 + row] = l1;
        }
    }
    {
        float4 b4[8];
        #pragma unroll
        for (int p = 0; p < 8; p++) b4[p] = ((const float4*)bP)[p];
        #pragma unroll
        for (int p = 0; p < 8; p++) {
            uint32_t h0, l0, h1, l1;
            bf16_split2(b4[p].x, b4[p].y, h0, l0);
            bf16_split2(b4[p].z, b4[p].w, h1, l1);
            BH[(pb + 2*p) * 136 + row] = h0;  BL[(pb + 2*p) * 136 + row] = l0;
            BH[(pb + 2*p + 1) * 136 + row] = h1;  BL[(pb + 2*p + 1) * 136 + row] = l1;
        }
    }
    __syncthreads();

    float acc[16][4];
    #pragma unroll
    for (int t = 0; t < 16; t++) { acc[t][0]=acc[t][1]=acc[t][2]=acc[t][3]=0.f; }

    #pragma unroll
    for (int g = 0; g < 4; g++) {
        const int p0 = g * 8 + pa;
        uint32_t bhf[4][2], blf[4][2];
        #pragma unroll
        for (int nt = 0; nt < 4; nt++) {
            const int n0 = wn + nt * 8 + lm;
            bhf[nt][0] = BH[p0 * 136 + n0];      bhf[nt][1] = BH[(p0+4) * 136 + n0];
            blf[nt][0] = BL[p0 * 136 + n0];      blf[nt][1] = BL[(p0+4) * 136 + n0];
        }
        #pragma unroll
        for (int mt = 0; mt < 4; mt++) {
            const int m0 = wm + mt * 16 + lm;
            uint32_t ah[4], al[4];
            ah[0] = AH[p0 * 136 + m0];     ah[1] = AH[p0 * 136 + m0 + 8];
            ah[2] = AH[(p0+4) * 136 + m0]; ah[3] = AH[(p0+4) * 136 + m0 + 8];
            al[0] = AL[p0 * 136 + m0];     al[1] = AL[p0 * 136 + m0 + 8];
            al[2] = AL[(p0+4) * 136 + m0]; al[3] = AL[(p0+4) * 136 + m0 + 8];
            #pragma unroll
            for (int nt = 0; nt < 4; nt++) {
                mma_bf16(acc[mt*4+nt], al, bhf[nt]);
                mma_bf16(acc[mt*4+nt], ah, blf[nt]);
                mma_bf16(acc[mt*4+nt], ah, bhf[nt]);
            }
        }
    }

    // ---- stage the 128x128 fp32 tile into smem (operands dead) --------------
    __syncthreads();
    float* ST = (float*)dsm;             // [128][132]  (132*4 = 528 B rows, 16B-aligned)
    #pragma unroll
    for (int mt = 0; mt < 4; mt++) {
        #pragma unroll
        for (int nt = 0; nt < 4; nt++) {
            const int r0 = wm + mt*16 + lm;
            const int c0 = wn + nt*8 + pa * 2;
            ST[r0 * 132 + c0]     = acc[mt*4+nt][0];
            ST[r0 * 132 + c0 + 1] = acc[mt*4+nt][1];
            ST[(r0+8) * 132 + c0]     = acc[mt*4+nt][2];
            ST[(r0+8) * 132 + c0 + 1] = acc[mt*4+nt][3];
        }
    }
    __syncthreads();

    // ---- coalesced global phase: warp owns 16 rows, lanes cover 128 cols ----
    float* Cbase = g_score + (size_t)z * S_LEN * K_LEN;
    #pragma unroll
    for (int rr = 0; rr < 16; rr++) {
        const int r = warp * 16 + rr;
        const int i = i0 + r;
        if (!IS_BD) {
            float4 vv = ((const float4*)(ST + r * 132))[lane];
            ((float4*)(Cbase + (size_t)i * K_LEN + j0))[lane] = vv;
        } else {
            const int base = j0 - (S_LEN - 1 - i);   // shifted col start
            float* gp = Cbase + (size_t)i * K_LEN;
            #pragma unroll
            for (int e = 0; e < 4; e++) {
                const int c = 4 * lane + e;
                const int j = base + c;
                if (j >= 0) gp[j] += ST[r * 132 + c];
            }
        }
    }
}

// =============================================================================
// Softmax: logits = score[i,j] / 8 over j in [0, i+m]; zero the masked tail.
// float4-vectorized, register-stashed: 1 read + 1 write of the row.
// =============================================================================
__global__ __launch_bounds__(256)
void softmax_kernel()
{
    const int rowid = blockIdx.x;              // z*S + i
    const int i = rowid & (S_LEN - 1);
    float* p = g_score + (size_t)rowid * K_LEN;
    const int jmax = i + M_MEM + 1;
    const int full4 = jmax >> 2;               // complete float4s
    const int tid = threadIdx.x;
    __shared__ float red[256];

    float l[16];
    float mx = -1e30f;
    #pragma unroll
    for (int t = 0; t < 4; t++) {
        const int q = tid + t * 256;           // float4 index, 0..1023
        if (q < full4) {
            float4 x = ((const float4*)p)[q];
            l[t*4+0] = x.x * 0.125f; l[t*4+1] = x.y * 0.125f;
            l[t*4+2] = x.z * 0.125f; l[t*4+3] = x.w * 0.125f;
            mx = fmaxf(mx, fmaxf(fmaxf(l[t*4+0], l[t*4+1]),
                                 fmaxf(l[t*4+2], l[t*4+3])));
        } else {
            #pragma unroll
            for (int e = 0; e < 4; e++) {
                const int j = q * 4 + e;
                if (j < jmax) {
                    l[t*4+e] = p[j] * 0.125f;
                    mx = fmaxf(mx, l[t*4+e]);
                }
            }
        }
    }
    red[tid] = mx; __syncthreads();
    for (int s = 128; s > 0; s >>= 1) {
        if (tid < s) red[tid] = fmaxf(red[tid], red[tid + s]);
        __syncthreads();
    }
    mx = red[0]; __syncthreads();

    float sum = 0.f;
    #pragma unroll
    for (int t = 0; t < 4; t++) {
        const int q = tid + t * 256;
        #pragma unroll
        for (int e = 0; e < 4; e++) {
            const int j = q * 4 + e;
            if (j < jmax) {
                const float ex = __expf(l[t*4+e] - mx);
                l[t*4+e] = ex;
                sum += ex;
            }
        }
    }
    red[tid] = sum; __syncthreads();
    for (int s = 128; s > 0; s >>= 1) {
        if (tid < s) red[tid] += red[tid + s];
        __syncthreads();
    }
    const float inv = 1.f / red[0];

    #pragma unroll
    for (int t = 0; t < 4; t++) {
        const int q = tid + t * 256;
        if (q < full4) {
            float4 x;
            x.x = l[t*4+0] * inv; x.y = l[t*4+1] * inv;
            x.z = l[t*4+2] * inv; x.w = l[t*4+3] * inv;
            ((float4*)p)[q] = x;
        } else {
            #pragma unroll
            for (int e = 0; e < 4; e++) {
                const int j = q * 4 + e;
                if (j < jmax) p[j] = l[t*4+e] * inv;
            }
        }
    }
    for (int j = jmax + tid; j < K_LEN; j += 256) p[j] = 0.f;
}

// =============================================================================
// attn = P @ V per z, 3xBF16, K-chunk 32. BM=128 (i), BN=64 (d), banded k.
// 8 warps 2x4, warp tile 64x16: MT=4, NT=2.
// =============================================================================
__global__ __launch_bounds__(256, 2)
void gemm_attnv()
{
    const int i0 = blockIdx.x * 128;
    const int z = blockIdx.y;
    const int b = z >> 3, h = z & 7;
    const int kmax = i0 + 127 + M_MEM + 1;     // multiple of 32

    __shared__ uint32_t Ah[16][136], Al[16][136];
    __shared__ uint32_t Bh[16][72],  Bl[16][72];

    const int tid = threadIdx.x, lane = tid & 31, warp = tid >> 5;
    const int wm = (warp >> 2) * 64, wn = (warp & 3) * 16;
    const int pa = lane & 3, lm = lane >> 2;

    const int arow = tid >> 1;           // i within tile
    const int ahalf = tid & 1;
    const int apb = ahalf * 8;
    const float* aP = g_score + ((size_t)z * S_LEN + i0 + arow) * K_LEN;

    const int pr = tid >> 4;             // V pair-row 0..15
    const int c4 = (tid & 15) * 4;       // d group of 4
    const float* vBase = g_qkv + ((size_t)(2 * pr) * B_SZ + b) * QKV3
                       + 2 * HI + h * I_DIM + c4;
    const size_t vRow = (size_t)B_SZ * QKV3;

    float acc[8][4];
    #pragma unroll
    for (int t = 0; t < 8; t++) { acc[t][0]=acc[t][1]=acc[t][2]=acc[t][3]=0.f; }

    for (int k0 = 0; k0 < kmax; k0 += 32) {
        // ---- P: 4 float4 batched (16 k)
        float4 a4[4];
        #pragma unroll
        for (int i = 0; i < 4; i++)
            a4[i] = *(const float4*)(aP + k0 + ahalf * 16 + 4 * i);
        #pragma unroll
        for (int i = 0; i < 4; i++) {
            uint32_t h0, l0, h1, l1;
            bf16_split2(a4[i].x, a4[i].y, h0, l0);
            bf16_split2(a4[i].z, a4[i].w, h1, l1);
            Ah[apb + 2*i][arow] = h0;  Al[apb + 2*i][arow] = l0;
            Ah[apb + 2*i + 1][arow] = h1;  Al[apb + 2*i + 1][arow] = l1;
        }
        // ---- V: rows k0+2pr, k0+2pr+1, cols c4..c4+3
        const float* vp = vBase + (size_t)k0 * vRow;
        float4 v0 = *(const float4*)vp;
        float4 v1 = *(const float4*)(vp + vRow);
        {
            uint32_t hh[4], ll[4];
            bf16_split2(v0.x, v1.x, hh[0], ll[0]);
            bf16_split2(v0.y, v1.y, hh[1], ll[1]);
            bf16_split2(v0.z, v1.z, hh[2], ll[2]);
            bf16_split2(v0.w, v1.w, hh[3], ll[3]);
            *(uint4*)&Bh[pr][c4] = make_uint4(hh[0], hh[1], hh[2], hh[3]);
            *(uint4*)&Bl[pr][c4] = make_uint4(ll[0], ll[1], ll[2], ll[3]);
        }
        __syncthreads();

        #pragma unroll
        for (int g = 0; g < 2; g++) {
            const int p0 = g * 8 + pa;
            uint32_t bhf[2][2], blf[2][2];
            #pragma unroll
            for (int nt = 0; nt < 2; nt++) {
                const int n0 = wn + nt * 8 + lm;
                bhf[nt][0] = Bh[p0][n0];   bhf[nt][1] = Bh[p0+4][n0];
                blf[nt][0] = Bl[p0][n0];   blf[nt][1] = Bl[p0+4][n0];
            }
            #pragma unroll
            for (int mt = 0; mt < 4; mt++) {
                const int m0 = wm + mt * 16 + lm;
                uint32_t ah[4], al[4];
                ah[0] = Ah[p0][m0];    ah[1] = Ah[p0][m0+8];
                ah[2] = Ah[p0+4][m0];  ah[3] = Ah[p0+4][m0+8];
                al[0] = Al[p0][m0];    al[1] = Al[p0][m0+8];
                al[2] = Al[p0+4][m0];  al[3] = Al[p0+4][m0+8];
                #pragma unroll
                for (int nt = 0; nt < 2; nt++) {
                    mma_bf16(acc[mt*2+nt], al, bhf[nt]);
                    mma_bf16(acc[mt*2+nt], ah, blf[nt]);
                    mma_bf16(acc[mt*2+nt], ah, bhf[nt]);
                }
            }
        }
        __syncthreads();
    }

    #pragma unroll
    for (int mt = 0; mt < 4; mt++) {
        #pragma unroll
        for (int nt = 0; nt < 2; nt++) {
            const int i = i0 + wm + mt*16 + lm;
            const int d = wn + nt*8 + pa * 2;
            float* cp = g_attn + ((size_t)i * B_SZ + b) * E_DIM + h * I_DIM + d;
            cp[0] = acc[mt*2+nt][0]; cp[1] = acc[mt*2+nt][1];
            float* cp2 = g_attn + ((size_t)(i+8) * B_SZ + b) * E_DIM + h * I_DIM + d;
            cp2[0] = acc[mt*2+nt][2]; cp2[1] = acc[mt*2+nt][3];
        }
    }
}

// ---------------- residual (+optional extra bias) + LayerNorm ----------------
__global__ __launch_bounds__(256)
void ln_kernel(const float* __restrict__ x1, const float* __restrict__ x2,
               const float* __restrict__ extra_bias,
               const float* __restrict__ gamma, const float* __restrict__ beta,
               float* __restrict__ out)
{
    const int row = blockIdx.x;
    const int tid = threadIdx.x;
    const float* p1 = x1 + (size_t)row * E_DIM;
    const float* p2 = x2 + (size_t)row * E_DIM;
    float v0 = p1[tid] + p2[tid];
    float v1 = p1[tid + 256] + p2[tid + 256];
    if (extra_bias) { v0 += extra_bias[tid]; v1 += extra_bias[tid + 256]; }

    __shared__ float red[256];
    red[tid] = v0 + v1; __syncthreads();
    for (int s = 128; s > 0; s >>= 1) {
        if (tid < s) red[tid] += red[tid + s];
        __syncthreads();
    }
    const float mean = red[0] * (1.f / E_DIM);
    __syncthreads();
    const float d0 = v0 - mean, d1 = v1 - mean;
    red[tid] = d0 * d0 + d1 * d1; __syncthreads();
    for (int s = 128; s > 0; s >>= 1) {
        if (tid < s) red[tid] += red[tid + s];
        __syncthreads();
    }
    const float rstd = rsqrtf(red[0] * (1.f / E_DIM) + 1e-5f);
    out[(size_t)row * E_DIM + tid]       = d0 * rstd * gamma[tid]       + beta[tid];
    out[(size_t)row * E_DIM + tid + 256] = d1 * rstd * gamma[tid + 256] + beta[tid + 256];
}

// ---------------- launch ------------------------------------------------------
extern "C" void kernel_launch(void* const* d_in, const int* in_sizes, int n_in,
                              void* d_out, int out_size)
{
    const float* inputDec = (const float*)d_in[0];
    const float* posEmb   = (const float*)d_in[1];
    const float* u        = (const float*)d_in[2];
    const float* v        = (const float*)d_in[3];
    const float* memories = (const float*)d_in[4];
    const float* Wqkv     = (const float*)d_in[5];
    const float* Wr       = (const float*)d_in[6];
    const float* Wo       = (const float*)d_in[7];
    const float* ln1_g    = (const float*)d_in[8];
    const float* ln1_b    = (const float*)d_in[9];
    const float* W1       = (const float*)d_in[10];
    const float* b1       = (const float*)d_in[11];
    const float* W2       = (const float*)d_in[12];
    const float* b2       = (const float*)d_in[13];
    const float* ln2_g    = (const float*)d_in[14];
    const float* ln2_b    = (const float*)d_in[15];
    float* out = (float*)d_out;

    float *p_qkv, *p_r, *p_attn, *p_y, *p_ao, *p_h, *p_z;
    cudaGetSymbolAddress((void**)&p_qkv, g_qkv);
    cudaGetSymbolAddress((void**)&p_r, g_r);
    cudaGetSymbolAddress((void**)&p_attn, g_attn);
    cudaGetSymbolAddress((void**)&p_y, g_y);
    cudaGetSymbolAddress((void**)&p_ao, g_ao);
    cudaGetSymbolAddress((void**)&p_h, g_hidden);
    cudaGetSymbolAddress((void**)&p_z, g_z);

    // Opt-in to >48KB dynamic smem for score kernels (idempotent, capture-safe)
    cudaFuncSetAttribute(gemm_score<0>,
        cudaFuncAttributeMaxDynamicSharedMemorySize, SCORE_SMEM_BYTES);
    cudaFuncSetAttribute(gemm_score<1>,
        cudaFuncAttributeMaxDynamicSharedMemorySize, SCORE_SMEM_BYTES);

    // 1) qkv = concat(memories, inputDec) @ Wqkv     (8192 x 1536 x 512)
    gemm_dense<0,0><<<dim3(QKV3 / 128, (K_LEN * B_SZ) / 128), 256>>>(
        memories, inputDec, M_MEM * B_SZ, Wqkv, nullptr, p_qkv, QKV3, E_DIM);

    // 2) r = posEmbeddings @ Wr                      (4096 x 512 x 512)
    gemm_dense<0,0><<<dim3(HI / 128, K_LEN / 128), 256>>>(
        posEmb, posEmb, K_LEN, Wr, nullptr, p_r, HI, E_DIM);

    // 3) AC score GEMM (stores), then BD GEMM (rel-shift add in epilogue)
    gemm_score<0><<<dim3(K_LEN / 128, S_LEN / 128, B_SZ * H_HEADS), 256,
                    SCORE_SMEM_BYTES>>>(u);
    gemm_score<1><<<dim3(K_LEN / 128, S_LEN / 128, B_SZ * H_HEADS), 256,
                    SCORE_SMEM_BYTES>>>(v);

    // 4) softmax
    softmax_kernel<<<B_SZ * H_HEADS * S_LEN, 256>>>();

    // 5) attn = P @ V
    gemm_attnv<<<dim3(S_LEN / 128, B_SZ * H_HEADS), 256>>>();

    // 6) y = attn @ Wo                               (4096 x 512 x 512)
    gemm_dense<0,0><<<dim3(E_DIM / 128, (S_LEN * B_SZ) / 128), 256>>>(
        p_attn, p_attn, S_LEN * B_SZ, Wo, nullptr, p_y, E_DIM, HI);

    // 7) attn_out = LN(inputDec + y)
    ln_kernel<<<S_LEN * B_SZ, 256>>>(inputDec, p_y, nullptr, ln1_g, ln1_b, p_ao);

    // 8) hidden = relu(attn_out @ W1 + b1)           (4096 x 2048 x 512)
    gemm_dense<1,1><<<dim3(FF_DIM / 128, (S_LEN * B_SZ) / 128), 256>>>(
        p_ao, p_ao, S_LEN * B_SZ, W1, b1, p_h, FF_DIM, E_DIM);

    // 9) z = hidden @ W2                             (4096 x 512 x 2048)
    gemm_dense<0,0><<<dim3(E_DIM / 128, (S_LEN * B_SZ) / 128), 256>>>(
        p_h, p_h, S_LEN * B_SZ, W2, nullptr, p_z, E_DIM, FF_DIM);

    // 10) out = LN(attn_out + z + b2)
    ln_kernel<<<S_LEN * B_SZ, 256>>>(p_ao, p_z, b2, ln2_g, ln2_b, out);
}